// round 13
// baseline (speedup 1.0000x reference)
#include <cuda_runtime.h>
#include <cuda_fp16.h>
#include <cstdint>
#include <cstddef>

// ---------------------------------------------------------------------------
// Problem constants
// ---------------------------------------------------------------------------
#define BATCH 8
#define CH    512
#define CQD   64
#define HW    4096
#define MTOT  832
#define MPAD  896

// scratch layout (float offsets)
#define OFF_W    0u
#define OFF_BI   425984u
#define OFF_WH   427008u
#define OFF_WL   656384u
#define OFF_XH   885760u
#define OFF_Y    17662976u
#define OFF_QTH  47023104u
#define OFF_KH   49120256u
#define OFF_VH   51217408u
#define OFF_PH   59606016u
#define OFF_PART 126714880u
#define OFF_ZINV 127763456u
#define OFF_CE   127796224u
#define OFF_CEP  127828992u
#define OFF_CO   128353280u
#define SCRATCH_FLOATS 130450432u

__device__ float g_scratch[SCRATCH_FLOATS];

// ---------------------------------------------------------------------------
// PTX helpers
// ---------------------------------------------------------------------------
__device__ __forceinline__ uint32_t smem_to_u32(const void* p) {
    uint32_t a;
    asm("{ .reg .u64 t; cvta.to.shared.u64 t, %1; cvt.u32.u64 %0, t; }" : "=r"(a) : "l"(p));
    return a;
}

__device__ __forceinline__ void ldsm4(uint32_t* r, uint32_t addr) {
    asm volatile("ldmatrix.sync.aligned.m8n8.x4.shared.b16 {%0,%1,%2,%3}, [%4];"
                 : "=r"(r[0]), "=r"(r[1]), "=r"(r[2]), "=r"(r[3]) : "r"(addr));
}
__device__ __forceinline__ void ldsm4t(uint32_t* r, uint32_t addr) {
    asm volatile("ldmatrix.sync.aligned.m8n8.x4.trans.shared.b16 {%0,%1,%2,%3}, [%4];"
                 : "=r"(r[0]), "=r"(r[1]), "=r"(r[2]), "=r"(r[3]) : "r"(addr));
}
__device__ __forceinline__ void mma16816(float* c, const uint32_t* a,
                                         uint32_t b0, uint32_t b1) {
    asm volatile("mma.sync.aligned.m16n8k16.row.col.f32.f16.f16.f32 "
                 "{%0,%1,%2,%3}, {%4,%5,%6,%7}, {%8,%9}, {%0,%1,%2,%3};"
                 : "+f"(c[0]), "+f"(c[1]), "+f"(c[2]), "+f"(c[3])
                 : "r"(a[0]), "r"(a[1]), "r"(a[2]), "r"(a[3]), "r"(b0), "r"(b1));
}
__device__ __forceinline__ void cp16(uint32_t dst, const void* src) {
    asm volatile("cp.async.cg.shared.global [%0], [%1], 16;" :: "r"(dst), "l"(src));
}
#define CP_COMMIT() asm volatile("cp.async.commit_group;" ::: "memory")

// ---------------------------------------------------------------------------
// Shared-template fp16-split GEMM (K1/K2 paths) — proven R8/R12 config.
// ---------------------------------------------------------------------------
template<int AT, int BK, int NST, int BN, int OCC>
__global__ void __launch_bounds__(256, OCC) gemm_mma(
    const __half* __restrict__ Ah, const __half* __restrict__ Al,
    const __half* __restrict__ Bh,
    const float* __restrict__ bias, float* __restrict__ C,
    int K, int lda, int ldb, int ldc,
    size_t sA, size_t sB, size_t sC, int has_bias,
    __half* __restrict__ QTo, __half* __restrict__ KHo, __half* __restrict__ VHo,
    __half* __restrict__ PEo, float* __restrict__ Part)
{
    constexpr int APITCH = BK + 8;
    constexpr int BPITCH = BN + 8;
    constexpr int A_STG  = 128 * APITCH * 2;
    constexpr int B_STG  = BK * BPITCH * 2;
    constexpr int STG_BYTES = AT * A_STG + B_STG;
    constexpr int ATPR  = BK / 8;
    constexpr int AROWS = 256 / ATPR;
    constexpr int NPASS = 128 / AROWS;
    constexpr int BTPR  = BN / 8;
    constexpr int BROWS = 256 / BTPR;
    constexpr int BPASS = BK / BROWS;
    constexpr int KS    = BK / 16;
    constexpr int NJ    = BN / 32;
    constexpr int WN    = BN / 2;

    extern __shared__ char smem[];
    __shared__ float sred[2][128];
    const uint32_t sb = smem_to_u32(smem);
    const int tid  = threadIdx.x;
    const int w    = tid >> 5, lane = tid & 31;
    const int wm   = w & 3,    wn   = w >> 2;
    const int b    = blockIdx.z;
    const int m0   = blockIdx.x * 128, n0 = blockIdx.y * BN;

    const __half* Ag[AT];
    Ag[0] = Ah + (size_t)b * sA + (size_t)m0 * lda;
    if (AT == 2) Ag[1] = Al + (size_t)b * sA + (size_t)m0 * lda;
    const __half* Bg0 = Bh + (size_t)b * sB + n0;

    const int nk = K / BK;

    const int a_row = tid / ATPR, a_ch = (tid % ATPR) << 3;
    const int b_row = tid / BTPR, b_ch = (tid % BTPR) << 3;

    auto issue = [&](int stage, int kt) {
        const uint32_t base = sb + stage * STG_BYTES;
        const int k0 = kt * BK;
#pragma unroll
        for (int h = 0; h < AT; h++) {
            const __half* asrc = Ag[h] + k0;
            const uint32_t adst = base + h * A_STG;
#pragma unroll
            for (int r = 0; r < NPASS; r++) {
                int row = a_row + r * AROWS;
                cp16(adst + (uint32_t)(row * APITCH + a_ch) * 2,
                     asrc + (size_t)row * lda + a_ch);
            }
        }
        {
            const uint32_t bdst = base + AT * A_STG;
#pragma unroll
            for (int r = 0; r < BPASS; r++) {
                int row = b_row + r * BROWS;
                cp16(bdst + (uint32_t)(row * BPITCH + b_ch) * 2,
                     Bg0 + (size_t)(k0 + row) * ldb + b_ch);
            }
        }
    };

    float c[2][2 * NJ][4];
#pragma unroll
    for (int mi = 0; mi < 2; mi++)
#pragma unroll
        for (int j = 0; j < 2 * NJ; j++)
#pragma unroll
            for (int q = 0; q < 4; q++) c[mi][j][q] = 0.0f;

#pragma unroll
    for (int s = 0; s < NST - 1; s++) {
        if (s < nk) issue(s, s);
        CP_COMMIT();
    }

    const uint32_t a_lane_off = (uint32_t)((lane & 15) * APITCH + ((lane >> 4) << 3)) * 2;
    const uint32_t b_lane_off = (uint32_t)((lane & 15) * BPITCH + ((lane >> 4) << 3)) * 2;

    for (int kt = 0; kt < nk; kt++) {
        const int kf = kt + NST - 1;
        if (kf < nk) issue(kf % NST, kf);
        CP_COMMIT();
        asm volatile("cp.async.wait_group %0;" :: "n"(NST - 1) : "memory");
        __syncthreads();

        const int stage = kt % NST;
        const uint32_t ab = sb + stage * STG_BYTES;
        const uint32_t bb = ab + AT * A_STG;

#pragma unroll
        for (int ks = 0; ks < KS; ks++) {
            uint32_t afr[AT][2][4];
            uint32_t bfr[NJ][4];
#pragma unroll
            for (int h = 0; h < AT; h++)
#pragma unroll
                for (int mi = 0; mi < 2; mi++)
                    ldsm4(afr[h][mi],
                          ab + h * A_STG + a_lane_off +
                          (uint32_t)((wm * 32 + mi * 16) * APITCH + ks * 16) * 2);
#pragma unroll
            for (int nj = 0; nj < NJ; nj++)
                ldsm4t(bfr[nj],
                       bb + b_lane_off +
                       (uint32_t)(ks * 16 * BPITCH + wn * WN + nj * 16) * 2);
#pragma unroll
            for (int mi = 0; mi < 2; mi++)
#pragma unroll
                for (int j = 0; j < 2 * NJ; j++) {
                    const int nj = j >> 1, hf = (j & 1) << 1;
                    mma16816(c[mi][j], afr[0][mi], bfr[nj][hf], bfr[nj][hf + 1]);
                    if (AT == 2)
                        mma16816(c[mi][j], afr[1][mi], bfr[nj][hf], bfr[nj][hf + 1]);
                }
        }
        __syncthreads();
    }

    // ---- epilogue ----
    const int colbase = n0 + wn * WN + (lane & 3) * 2;
    if (KHo != nullptr) {
#pragma unroll
        for (int mi = 0; mi < 2; mi++)
#pragma unroll
            for (int rr = 0; rr < 2; rr++) {
                const int row = m0 + wm * 32 + mi * 16 + (lane >> 2) + rr * 8;
                if (row >= MTOT) continue;
                const float bv = bias[row];
                if (row < 64) {
                    __half* qb = QTo + (size_t)b * HW * 64 + row;
#pragma unroll
                    for (int j = 0; j < 2 * NJ; j++) {
                        const int col = colbase + j * 8;
                        qb[(size_t)col * 64]       =
                            __float2half_rn(c[mi][j][rr * 2] + bv);
                        qb[(size_t)(col + 1) * 64] =
                            __float2half_rn(c[mi][j][rr * 2 + 1] + bv);
                    }
                } else if (row < 128) {
                    __half* ph = KHo + ((size_t)b * 64 + (row - 64)) * HW + colbase;
#pragma unroll
                    for (int j = 0; j < 2 * NJ; j++)
                        *reinterpret_cast<__half2*>(ph + j * 8) = __halves2half2(
                            __float2half_rn(c[mi][j][rr * 2] + bv),
                            __float2half_rn(c[mi][j][rr * 2 + 1] + bv));
                } else if (row < 640) {
                    __half* ph = VHo + ((size_t)b * 512 + (row - 128)) * HW + colbase;
#pragma unroll
                    for (int j = 0; j < 2 * NJ; j++)
                        *reinterpret_cast<__half2*>(ph + j * 8) = __halves2half2(
                            __float2half_rn(c[mi][j][rr * 2] + bv),
                            __float2half_rn(c[mi][j][rr * 2 + 1] + bv));
                } else {
                    float* p = C + (size_t)b * sC + (size_t)row * ldc + colbase;
#pragma unroll
                    for (int j = 0; j < 2 * NJ; j++)
                        *reinterpret_cast<float2*>(p + j * 8) =
                            make_float2(c[mi][j][rr * 2] + bv, c[mi][j][rr * 2 + 1] + bv);
                }
            }
    } else if (PEo != nullptr) {
#pragma unroll
        for (int mi = 0; mi < 2; mi++)
#pragma unroll
            for (int rr = 0; rr < 2; rr++) {
                const int rloc = wm * 32 + mi * 16 + (lane >> 2) + rr * 8;
                __half* pp = PEo + ((size_t)b * HW + m0 + rloc) * HW + colbase;
                float rsum = 0.0f;
#pragma unroll
                for (int j = 0; j < 2 * NJ; j++) {
                    float e0 = __expf(c[mi][j][rr * 2]     - 8.0f);
                    float e1 = __expf(c[mi][j][rr * 2 + 1] - 8.0f);
                    __half h0 = __float2half_rn(e0), h1 = __float2half_rn(e1);
                    *reinterpret_cast<__half2*>(pp + j * 8) = __halves2half2(h0, h1);
                    rsum += __half2float(h0) + __half2float(h1);
                }
                rsum += __shfl_xor_sync(0xffffffffu, rsum, 1);
                rsum += __shfl_xor_sync(0xffffffffu, rsum, 2);
                if ((lane & 3) == 0) sred[wn][rloc] = rsum;
            }
        __syncthreads();
        if (tid < 128) {
            float z = sred[0][tid] + sred[1][tid];
            Part[((size_t)b * gridDim.y + blockIdx.y) * HW + m0 + tid] = z;
        }
    } else {
#pragma unroll
        for (int mi = 0; mi < 2; mi++) {
            const int r0 = m0 + wm * 32 + mi * 16 + (lane >> 2);
            const float bv0 = has_bias ? bias[r0]     : 0.0f;
            const float bv1 = has_bias ? bias[r0 + 8] : 0.0f;
            float* p0 = C + (size_t)b * sC + (size_t)r0 * ldc + colbase;
            float* p1 = p0 + (size_t)8 * ldc;
#pragma unroll
            for (int j = 0; j < 2 * NJ; j++) {
                *reinterpret_cast<float2*>(p0 + j * 8) =
                    make_float2(c[mi][j][0] + bv0, c[mi][j][1] + bv0);
                *reinterpret_cast<float2*>(p1 + j * 8) =
                    make_float2(c[mi][j][2] + bv1, c[mi][j][3] + bv1);
            }
        }
    }
}

#define SM_AT2 (3 * (2 * 128 * 40 * 2 + 32 * 136 * 2))   // 87552
#define SM_AT1 (3 * (1 * 128 * 40 * 2 + 32 * 136 * 2))   // 56832

// ---------------------------------------------------------------------------
// K4-dedicated GEMM: CTA 256x128, warp tile 64x64 (4m x 2n warps), BK=32,
// NST=3, 1 CTA/SM. 32 mma per 8 ldsm per k-step -> higher tensor-issue ratio.
// C[b] = A[b] @ B[b], plain fp32 epilogue. Same per-element k order as before.
// ---------------------------------------------------------------------------
#define BIG_APITCH 40
#define BIG_BPITCH 136
#define BIG_A_STG  (256 * BIG_APITCH * 2)     // 20480
#define BIG_B_STG  (32 * BIG_BPITCH * 2)      // 8704
#define BIG_STG    (BIG_A_STG + BIG_B_STG)    // 29184
#define SM_BIG     (3 * BIG_STG)              // 87552

__global__ void __launch_bounds__(256, 1) gemm_big(
    const __half* __restrict__ A, const __half* __restrict__ Bh,
    float* __restrict__ C, int K, int lda, int ldb, int ldc,
    size_t sA, size_t sB, size_t sC)
{
    extern __shared__ char smem[];
    const uint32_t sb = smem_to_u32(smem);
    const int tid  = threadIdx.x;
    const int w    = tid >> 5, lane = tid & 31;
    const int wm   = w & 3,    wn   = w >> 2;     // 4 m-warps x 2 n-warps
    const int b    = blockIdx.z;
    const int m0   = blockIdx.x * 256, n0 = blockIdx.y * 128;

    const __half* Ag = A  + (size_t)b * sA + (size_t)m0 * lda;
    const __half* Bg = Bh + (size_t)b * sB + n0;

    const int nk = K >> 5;

    const int a_row = tid >> 2, a_ch = (tid & 3) << 3;   // 64 rows/pass, 4 passes
    const int b_row = tid >> 4, b_ch = (tid & 15) << 3;  // 16 rows/pass, 2 passes

    auto issue = [&](int stage, int kt) {
        const uint32_t base = sb + stage * BIG_STG;
        const int k0 = kt << 5;
#pragma unroll
        for (int r = 0; r < 4; r++) {
            int row = a_row + r * 64;
            cp16(base + (uint32_t)(row * BIG_APITCH + a_ch) * 2,
                 Ag + (size_t)row * lda + k0 + a_ch);
        }
        const uint32_t bdst = base + BIG_A_STG;
#pragma unroll
        for (int r = 0; r < 2; r++) {
            int row = b_row + r * 16;
            cp16(bdst + (uint32_t)(row * BIG_BPITCH + b_ch) * 2,
                 Bg + (size_t)(k0 + row) * ldb + b_ch);
        }
    };

    float c[4][8][4];
#pragma unroll
    for (int mi = 0; mi < 4; mi++)
#pragma unroll
        for (int j = 0; j < 8; j++)
#pragma unroll
            for (int q = 0; q < 4; q++) c[mi][j][q] = 0.0f;

    issue(0, 0); CP_COMMIT();
    if (nk > 1) issue(1, 1);
    CP_COMMIT();

    const uint32_t a_lane_off = (uint32_t)((lane & 15) * BIG_APITCH + ((lane >> 4) << 3)) * 2;
    const uint32_t b_lane_off = (uint32_t)((lane & 15) * BIG_BPITCH + ((lane >> 4) << 3)) * 2;

    for (int kt = 0; kt < nk; kt++) {
        const int kf = kt + 2;
        if (kf < nk) issue(kf % 3, kf);
        CP_COMMIT();
        asm volatile("cp.async.wait_group 2;" ::: "memory");
        __syncthreads();

        const uint32_t ab = sb + (kt % 3) * BIG_STG;
        const uint32_t bb = ab + BIG_A_STG;

#pragma unroll
        for (int ks = 0; ks < 2; ks++) {
            uint32_t afr[4][4];
            uint32_t bfr[4][4];
#pragma unroll
            for (int mi = 0; mi < 4; mi++)
                ldsm4(afr[mi],
                      ab + a_lane_off +
                      (uint32_t)((wm * 64 + mi * 16) * BIG_APITCH + ks * 16) * 2);
#pragma unroll
            for (int nj = 0; nj < 4; nj++)
                ldsm4t(bfr[nj],
                       bb + b_lane_off +
                       (uint32_t)(ks * 16 * BIG_BPITCH + wn * 64 + nj * 16) * 2);
#pragma unroll
            for (int mi = 0; mi < 4; mi++)
#pragma unroll
                for (int j = 0; j < 8; j++) {
                    const int nj = j >> 1, hf = (j & 1) << 1;
                    mma16816(c[mi][j], afr[mi], bfr[nj][hf], bfr[nj][hf + 1]);
                }
        }
        __syncthreads();
    }

    // ---- epilogue: plain fp32 ----
    const int colbase = n0 + wn * 64 + (lane & 3) * 2;
#pragma unroll
    for (int mi = 0; mi < 4; mi++) {
        const int r0 = m0 + wm * 64 + mi * 16 + (lane >> 2);
        float* p0 = C + (size_t)b * sC + (size_t)r0 * ldc + colbase;
        float* p1 = p0 + (size_t)8 * ldc;
#pragma unroll
        for (int j = 0; j < 8; j++) {
            *reinterpret_cast<float2*>(p0 + j * 8) = make_float2(c[mi][j][0], c[mi][j][1]);
            *reinterpret_cast<float2*>(p1 + j * 8) = make_float2(c[mi][j][2], c[mi][j][3]);
        }
    }
}

// ---------------------------------------------------------------------------
// Z reduction + v column scaling
// ---------------------------------------------------------------------------
__global__ void zinv_k(const float* __restrict__ Part, float* __restrict__ zinv)
{
    int i = blockIdx.x * 256 + threadIdx.x;
    int b = i >> 12, r = i & 4095;
    float s = 0.0f;
#pragma unroll
    for (int jt = 0; jt < 32; jt++) s += Part[((size_t)b * 32 + jt) * HW + r];
    zinv[i] = 1.0f / s;
}

__global__ void vscale_k(__half* __restrict__ VH, const float* __restrict__ zinv)
{
    const int b = blockIdx.y;
    int idx = blockIdx.x * 256 + threadIdx.x;
    int c  = idx >> 11;
    int i2 = idx & 2047;
    __half2* p = reinterpret_cast<__half2*>(VH + ((size_t)b * 512 + c) * HW) + i2;
    float2 f = __half22float2(*p);
    float z0 = zinv[(size_t)b * HW + 2 * i2];
    float z1 = zinv[(size_t)b * HW + 2 * i2 + 1];
    *p = __floats2half2_rn(f.x * z0, f.y * z1);
}

// ---------------------------------------------------------------------------
// fp16 conversions
// ---------------------------------------------------------------------------
__global__ void tohalf4(const float* __restrict__ in, __half* __restrict__ hi,
                        int count4, size_t in_bs, size_t out_bs)
{
    size_t b = blockIdx.y;
    int i = blockIdx.x * 256 + threadIdx.x;
    if (i >= count4) return;
    float4 v = reinterpret_cast<const float4*>(in + b * in_bs)[i];
    __half2* ph = reinterpret_cast<__half2*>(hi + b * out_bs);
    ph[2 * i]     = __floats2half2_rn(v.x, v.y);
    ph[2 * i + 1] = __floats2half2_rn(v.z, v.w);
}

__global__ void splitW(const float* __restrict__ in, __half* __restrict__ hi,
                       __half* __restrict__ lo)
{
    int i = blockIdx.x * 256 + threadIdx.x;
    float v = (i < MTOT * CH) ? in[i] : 0.0f;
    __half h = __float2half_rn(v);
    hi[i] = h;
    lo[i] = __float2half_rn(v - __half2float(h));
}

// ---------------------------------------------------------------------------
// SIMT f32x2 GEMM (small K8 accumulate)
// ---------------------------------------------------------------------------
__device__ __forceinline__ unsigned long long pk2(float lo, float hi) {
    unsigned long long r;
    asm("mov.b64 %0, {%1, %2};" : "=l"(r) : "f"(lo), "f"(hi));
    return r;
}
__device__ __forceinline__ unsigned long long fma2(unsigned long long a,
                                                   unsigned long long b,
                                                   unsigned long long c) {
    unsigned long long d;
    asm("fma.rn.f32x2 %0, %1, %2, %3;" : "=l"(d) : "l"(a), "l"(b), "l"(c));
    return d;
}
__device__ __forceinline__ float2 u2f(unsigned long long u) {
    float2 f;
    asm("mov.b64 {%0, %1}, %2;" : "=f"(f.x), "=f"(f.y) : "l"(u));
    return f;
}

__global__ __launch_bounds__(256, 2)
void gemm_acc(const float* __restrict__ A, const float* __restrict__ Bm,
              const float* __restrict__ bias, float* __restrict__ Cm,
              int M, int N, int K, int lda, int ldb, int ldc,
              size_t sA, size_t sB, size_t sC)
{
    __shared__ float As[16][128 + 4];
    __shared__ float Bs[16][128];

    const int b  = blockIdx.z;
    const float* Ab = A + (size_t)b * sA;
    const float* Bb = Bm + (size_t)b * sB;
    float*       Cb = Cm + (size_t)b * sC;

    const int m0 = blockIdx.y * 128;
    const int n0 = blockIdx.x * 128;
    const int t  = threadIdx.x;
    const int tm0 = (t >> 4) << 3;
    const int tn0 = (t & 15) << 3;

    unsigned long long acc[8][4];
#pragma unroll
    for (int i = 0; i < 8; i++)
#pragma unroll
        for (int j = 0; j < 4; j++) acc[i][j] = 0ull;

    for (int k0 = 0; k0 < K; k0 += 16) {
#pragma unroll
        for (int r = 0; r < 2; r++) {
            int idx = t + r * 256;
            int row = idx >> 2;
            int c4  = (idx & 3) << 2;
            float4 v = make_float4(0.f, 0.f, 0.f, 0.f);
            if (m0 + row < M)
                v = *reinterpret_cast<const float4*>(Ab + (size_t)(m0 + row) * lda + k0 + c4);
            As[c4 + 0][row] = v.x; As[c4 + 1][row] = v.y;
            As[c4 + 2][row] = v.z; As[c4 + 3][row] = v.w;
        }
#pragma unroll
        for (int r = 0; r < 2; r++) {
            int idx = t + r * 256;
            int kr  = idx >> 5;
            int n4  = (idx & 31) << 2;
            float4 v = *reinterpret_cast<const float4*>(Bb + (size_t)(k0 + kr) * ldb + n0 + n4);
            *reinterpret_cast<float4*>(&Bs[kr][n4]) = v;
        }
        __syncthreads();
#pragma unroll
        for (int kk = 0; kk < 16; kk++) {
            float4 a0 = *reinterpret_cast<const float4*>(&As[kk][tm0]);
            float4 a1 = *reinterpret_cast<const float4*>(&As[kk][tm0 + 4]);
            ulonglong2 bl0 = *reinterpret_cast<const ulonglong2*>(&Bs[kk][tn0]);
            ulonglong2 bl1 = *reinterpret_cast<const ulonglong2*>(&Bs[kk][tn0 + 4]);
            unsigned long long bv[4] = {bl0.x, bl0.y, bl1.x, bl1.y};
            float av[8] = {a0.x, a0.y, a0.z, a0.w, a1.x, a1.y, a1.z, a1.w};
#pragma unroll
            for (int i = 0; i < 8; i++) {
                unsigned long long a2 = pk2(av[i], av[i]);
#pragma unroll
                for (int j = 0; j < 4; j++) acc[i][j] = fma2(a2, bv[j], acc[i][j]);
            }
        }
        __syncthreads();
    }
#pragma unroll
    for (int i = 0; i < 8; i++) {
        int m = m0 + tm0 + i;
        if (m >= M) continue;
        float bsv = bias[m];
        float* crow = Cb + (size_t)m * ldc + n0 + tn0;
#pragma unroll
        for (int j = 0; j < 4; j++) {
            float2 f = u2f(acc[i][j]);
            float2 o = *reinterpret_cast<const float2*>(crow + j * 2);
            f.x += bsv + o.x; f.y += bsv + o.y;
            *reinterpret_cast<float2*>(crow + j * 2) = f;
        }
    }
}

// ---------------------------------------------------------------------------
// Channel attention kernels (fp32, small)
// ---------------------------------------------------------------------------
__global__ void chan_energy(const float* __restrict__ cq, const float* __restrict__ ck,
                            float* __restrict__ part)
{
    __shared__ float sq[64][65];
    __shared__ float sk[64][65];
    const int b = blockIdx.y;
    const int split = blockIdx.x;
    const float* cqb = cq + (size_t)b * MPAD * HW;
    const float* ckb = ck + (size_t)b * MPAD * HW;
    const int t = threadIdx.x;
    const int p0 = (t >> 4) * 4;
    const int q0 = (t & 15) * 4;

    float acc[4][4];
#pragma unroll
    for (int i = 0; i < 4; i++)
#pragma unroll
        for (int j = 0; j < 4; j++) acc[i][j] = 0.f;

    for (int c = 0; c < 4; c++) {
        const int nb = (split * 4 + c) * 64;
        __syncthreads();
#pragma unroll
        for (int i = 0; i < 16; i++) {
            int idx = t + i * 256;
            int row = idx >> 6, col = idx & 63;
            sq[row][col] = cqb[(size_t)row * HW + nb + col];
            sk[row][col] = ckb[(size_t)row * HW + nb + col];
        }
        __syncthreads();
        for (int nn = 0; nn < 64; nn++) {
            float aq[4], bk[4];
#pragma unroll
            for (int i = 0; i < 4; i++) aq[i] = sq[p0 + i][nn];
#pragma unroll
            for (int j = 0; j < 4; j++) bk[j] = sk[q0 + j][nn];
#pragma unroll
            for (int i = 0; i < 4; i++)
#pragma unroll
                for (int j = 0; j < 4; j++) acc[i][j] += aq[i] * bk[j];
        }
    }
    float* out = part + (size_t)split * (BATCH * 4096) + (size_t)b * 4096;
#pragma unroll
    for (int i = 0; i < 4; i++)
#pragma unroll
        for (int j = 0; j < 4; j++)
            out[(p0 + i) * 64 + (q0 + j)] = acc[i][j];
}

__global__ void reduce_ce(const float* __restrict__ part, float* __restrict__ cE)
{
    int i = blockIdx.x * 256 + threadIdx.x;
    float s = 0.f;
#pragma unroll
    for (int k = 0; k < 16; k++) s += part[(size_t)k * (BATCH * 4096) + i];
    cE[i] = s;
}

__global__ void chan_softmax(float* __restrict__ cE)
{
    __shared__ float red[64];
    const int row = blockIdx.x;
    float* rp = cE + (size_t)row * 64;
    const int t = threadIdx.x;
    float v = rp[t];
    red[t] = v; __syncthreads();
    for (int s = 32; s > 0; s >>= 1) {
        if (t < s) red[t] = fmaxf(red[t], red[t + s]);
        __syncthreads();
    }
    float m = red[0]; __syncthreads();
    float e = __expf(v - m);
    red[t] = e; __syncthreads();
    for (int s = 32; s > 0; s >>= 1) {
        if (t < s) red[t] += red[t + s];
        __syncthreads();
    }
    rp[t] = e / red[0];
}

__global__ void chan_out(const float* __restrict__ cattn, const float* __restrict__ cv,
                         float* __restrict__ cout)
{
    __shared__ float sa[4096];
    const int b = blockIdx.y;
    const int n = blockIdx.x * 256 + threadIdx.x;
    const float* at = cattn + (size_t)b * 4096;
    for (int i = threadIdx.x; i < 4096; i += 256) sa[i] = at[i];
    __syncthreads();

    const float* cvb = cv + (size_t)b * MPAD * HW;
    float acc[64];
#pragma unroll
    for (int p = 0; p < 64; p++) acc[p] = 0.f;
    for (int q = 0; q < 64; q++) {
        float vv = cvb[(size_t)q * HW + n];
#pragma unroll
        for (int p = 0; p < 64; p++) acc[p] += sa[p * 64 + q] * vv;
    }
    float* ob = cout + (size_t)b * CQD * HW;
#pragma unroll
    for (int p = 0; p < 64; p++) ob[(size_t)p * HW + n] = acc[p];
}

// ---------------------------------------------------------------------------
// Launch (two-stream fork/join: channel path overlaps K2/K4)
// ---------------------------------------------------------------------------
extern "C" void kernel_launch(void* const* d_in, const int* in_sizes, int n_in,
                              void* d_out, int out_size)
{
    (void)in_sizes; (void)n_in; (void)out_size;

    static cudaStream_t s2 = nullptr;
    static cudaEvent_t evFork = nullptr, evJoin = nullptr;
    if (s2 == nullptr) {
        cudaStreamCreateWithFlags(&s2, cudaStreamNonBlocking);
        cudaEventCreateWithFlags(&evFork, cudaEventDisableTiming);
        cudaEventCreateWithFlags(&evJoin, cudaEventDisableTiming);
    }

    const float* x = (const float*)d_in[0];

    float* S = nullptr;
    cudaGetSymbolAddress((void**)&S, g_scratch);

    float* W    = S + OFF_W;
    float* BI   = S + OFF_BI;
    float* Y    = S + OFF_Y;
    float* PART = S + OFF_PART;
    float* ZINV = S + OFF_ZINV;
    float* CE   = S + OFF_CE;
    float* CEP  = S + OFF_CEP;
    float* CO   = S + OFF_CO;
    float* out  = (float*)d_out;

    __half* WH  = (__half*)(S + OFF_WH);
    __half* WL  = (__half*)(S + OFF_WL);
    __half* XH  = (__half*)(S + OFF_XH);
    __half* QTH = (__half*)(S + OFF_QTH);
    __half* KH  = (__half*)(S + OFF_KH);
    __half* VH  = (__half*)(S + OFF_VH);
    __half* PH  = (__half*)(S + OFF_PH);

    // pack fp32 weights + bias
    cudaMemcpyAsync(W +      0, d_in[1],  64  * 512 * sizeof(float), cudaMemcpyDeviceToDevice);
    cudaMemcpyAsync(W +  32768, d_in[3],  64  * 512 * sizeof(float), cudaMemcpyDeviceToDevice);
    cudaMemcpyAsync(W +  65536, d_in[5],  512 * 512 * sizeof(float), cudaMemcpyDeviceToDevice);
    cudaMemcpyAsync(W + 327680, d_in[7],  64  * 512 * sizeof(float), cudaMemcpyDeviceToDevice);
    cudaMemcpyAsync(W + 360448, d_in[9],  64  * 512 * sizeof(float), cudaMemcpyDeviceToDevice);
    cudaMemcpyAsync(W + 393216, d_in[11], 64  * 512 * sizeof(float), cudaMemcpyDeviceToDevice);
    cudaMemcpyAsync(BI +   0, d_in[2],  64  * sizeof(float), cudaMemcpyDeviceToDevice);
    cudaMemcpyAsync(BI +  64, d_in[4],  64  * sizeof(float), cudaMemcpyDeviceToDevice);
    cudaMemcpyAsync(BI + 128, d_in[6],  512 * sizeof(float), cudaMemcpyDeviceToDevice);
    cudaMemcpyAsync(BI + 640, d_in[8],  64  * sizeof(float), cudaMemcpyDeviceToDevice);
    cudaMemcpyAsync(BI + 704, d_in[10], 64  * sizeof(float), cudaMemcpyDeviceToDevice);
    cudaMemcpyAsync(BI + 768, d_in[12], 64  * sizeof(float), cudaMemcpyDeviceToDevice);

    cudaFuncSetAttribute((const void*)gemm_mma<2, 32, 3, 128, 2>,
                         cudaFuncAttributeMaxDynamicSharedMemorySize, SM_AT2);
    cudaFuncSetAttribute((const void*)gemm_mma<1, 32, 3, 128, 2>,
                         cudaFuncAttributeMaxDynamicSharedMemorySize, SM_AT1);
    cudaFuncSetAttribute((const void*)gemm_big,
                         cudaFuncAttributeMaxDynamicSharedMemorySize, SM_BIG);

    // fp16 conversions: W split, x single
    splitW<<<(MPAD * CH + 255) / 256, 256>>>(W, WH, WL);
    tohalf4<<<dim3(2048, BATCH), 256>>>(x, XH, 524288, (size_t)CH * HW, (size_t)CH * HW);

    // K1: projections (2-term), routed epilogue
    gemm_mma<2, 32, 3, 128, 2><<<dim3(7, 32, BATCH), 256, SM_AT2>>>(
        WH, WL, XH, BI, Y, 512, 512, HW, HW,
        (size_t)0, (size_t)CH * HW, (size_t)MPAD * HW, 1, QTH, KH, VH,
        nullptr, nullptr);

    // ---- fork: channel path on s2 ----
    cudaEventRecord(evFork, 0);
    cudaStreamWaitEvent(s2, evFork, 0);

    chan_energy<<<dim3(16, BATCH), 256, 0, s2>>>(
        Y + (size_t)640 * HW, Y + (size_t)704 * HW, CEP);
    reduce_ce<<<128, 256, 0, s2>>>(CEP, CE);
    chan_softmax<<<BATCH * 64, 64, 0, s2>>>(CE);
    chan_out<<<dim3(16, BATCH), 256, 0, s2>>>(CE, Y + (size_t)768 * HW, CO);
    cudaEventRecord(evJoin, s2);

    // ---- main stream: position path ----
    gemm_mma<1, 32, 3, 128, 2><<<dim3(32, 32, BATCH), 256, SM_AT1>>>(
        QTH, nullptr, KH, nullptr, nullptr, 64, 64, HW, 0,
        (size_t)HW * 64, (size_t)64 * HW, (size_t)0, 0,
        nullptr, nullptr, nullptr, PH, PART);

    zinv_k<<<BATCH * HW / 256, 256>>>(PART, ZINV);
    vscale_k<<<dim3(4096, BATCH), 256>>>(VH, ZINV);

    // K4: pos_out = vscaled @ PE  (dedicated 256x128 CTA, warp 64x64)
    gemm_big<<<dim3(2, 32, BATCH), 256, SM_BIG>>>(
        VH, PH, out, HW, HW, HW, HW,
        (size_t)CH * HW, (size_t)HW * HW, (size_t)CH * HW);

    // ---- join ----
    cudaStreamWaitEvent(0, evJoin, 0);

    // K8: d_out += co_w @ c_out + co_b (SIMT)
    gemm_acc<<<dim3(32, 4, BATCH), 256>>>(
        (const float*)d_in[13], CO, (const float*)d_in[14], out,
        CH, HW, CQD, CQD, HW, HW,
        (size_t)0, (size_t)CQD * HW, (size_t)CH * HW);
}

// round 14
// speedup vs baseline: 1.1059x; 1.1059x over previous
#include <cuda_runtime.h>
#include <cuda_fp16.h>
#include <cstdint>
#include <cstddef>

// ---------------------------------------------------------------------------
// Problem constants
// ---------------------------------------------------------------------------
#define BATCH 8
#define CH    512
#define CQD   64
#define HW    4096
#define MTOT  832
#define MPAD  896

// scratch layout (float offsets)
#define OFF_W    0u
#define OFF_BI   425984u
#define OFF_WH   427008u
#define OFF_WL   656384u
#define OFF_XH   885760u
#define OFF_Y    17662976u
#define OFF_QTH  47023104u
#define OFF_KH   49120256u
#define OFF_VH   51217408u
#define OFF_PH   59606016u
#define OFF_PART 126714880u
#define OFF_ZINV 127763456u
#define OFF_CE   127796224u
#define OFF_CEP  127828992u
#define OFF_CO   128353280u    // c_out fp32 [8,64,4096]
#define OFF_CY   130450432u    // channel output CY fp32 [8,512,4096]
#define SCRATCH_FLOATS 147227648u

__device__ float g_scratch[SCRATCH_FLOATS];

// ---------------------------------------------------------------------------
// PTX helpers
// ---------------------------------------------------------------------------
__device__ __forceinline__ uint32_t smem_to_u32(const void* p) {
    uint32_t a;
    asm("{ .reg .u64 t; cvta.to.shared.u64 t, %1; cvt.u32.u64 %0, t; }" : "=r"(a) : "l"(p));
    return a;
}

__device__ __forceinline__ void ldsm4(uint32_t* r, uint32_t addr) {
    asm volatile("ldmatrix.sync.aligned.m8n8.x4.shared.b16 {%0,%1,%2,%3}, [%4];"
                 : "=r"(r[0]), "=r"(r[1]), "=r"(r[2]), "=r"(r[3]) : "r"(addr));
}
__device__ __forceinline__ void ldsm4t(uint32_t* r, uint32_t addr) {
    asm volatile("ldmatrix.sync.aligned.m8n8.x4.trans.shared.b16 {%0,%1,%2,%3}, [%4];"
                 : "=r"(r[0]), "=r"(r[1]), "=r"(r[2]), "=r"(r[3]) : "r"(addr));
}
__device__ __forceinline__ void mma16816(float* c, const uint32_t* a,
                                         uint32_t b0, uint32_t b1) {
    asm volatile("mma.sync.aligned.m16n8k16.row.col.f32.f16.f16.f32 "
                 "{%0,%1,%2,%3}, {%4,%5,%6,%7}, {%8,%9}, {%0,%1,%2,%3};"
                 : "+f"(c[0]), "+f"(c[1]), "+f"(c[2]), "+f"(c[3])
                 : "r"(a[0]), "r"(a[1]), "r"(a[2]), "r"(a[3]), "r"(b0), "r"(b1));
}
__device__ __forceinline__ void cp16(uint32_t dst, const void* src) {
    asm volatile("cp.async.cg.shared.global [%0], [%1], 16;" :: "r"(dst), "l"(src));
}
#define CP_COMMIT() asm volatile("cp.async.commit_group;" ::: "memory")

// ---------------------------------------------------------------------------
// fp16-split GEMM via mma.sync (HMMA) — proven R8/R12 config.
//   AT = A terms; BK/NST/BN/OCC tile params.
// Epilogue modes:
//   KHo != nullptr : K1 routed projection epilogue
//   PEo != nullptr : K2 exp epilogue (PE fp16 + row-sum partials)
//   else           : fp32 C (+bias if has_bias; +Cadd[m][n] if Cadd != nullptr)
// ---------------------------------------------------------------------------
template<int AT, int BK, int NST, int BN, int OCC>
__global__ void __launch_bounds__(256, OCC) gemm_mma(
    const __half* __restrict__ Ah, const __half* __restrict__ Al,
    const __half* __restrict__ Bh,
    const float* __restrict__ bias, float* __restrict__ C,
    int K, int lda, int ldb, int ldc,
    size_t sA, size_t sB, size_t sC, int has_bias,
    __half* __restrict__ QTo, __half* __restrict__ KHo, __half* __restrict__ VHo,
    __half* __restrict__ PEo, float* __restrict__ Part,
    const float* __restrict__ Cadd)
{
    constexpr int APITCH = BK + 8;
    constexpr int BPITCH = BN + 8;
    constexpr int A_STG  = 128 * APITCH * 2;
    constexpr int B_STG  = BK * BPITCH * 2;
    constexpr int STG_BYTES = AT * A_STG + B_STG;
    constexpr int ATPR  = BK / 8;
    constexpr int AROWS = 256 / ATPR;
    constexpr int NPASS = 128 / AROWS;
    constexpr int BTPR  = BN / 8;
    constexpr int BROWS = 256 / BTPR;
    constexpr int BPASS = BK / BROWS;
    constexpr int KS    = BK / 16;
    constexpr int NJ    = BN / 32;
    constexpr int WN    = BN / 2;

    extern __shared__ char smem[];
    __shared__ float sred[2][128];
    const uint32_t sb = smem_to_u32(smem);
    const int tid  = threadIdx.x;
    const int w    = tid >> 5, lane = tid & 31;
    const int wm   = w & 3,    wn   = w >> 2;
    const int b    = blockIdx.z;
    const int m0   = blockIdx.x * 128, n0 = blockIdx.y * BN;

    const __half* Ag[AT];
    Ag[0] = Ah + (size_t)b * sA + (size_t)m0 * lda;
    if (AT == 2) Ag[1] = Al + (size_t)b * sA + (size_t)m0 * lda;
    const __half* Bg0 = Bh + (size_t)b * sB + n0;

    const int nk = K / BK;

    const int a_row = tid / ATPR, a_ch = (tid % ATPR) << 3;
    const int b_row = tid / BTPR, b_ch = (tid % BTPR) << 3;

    auto issue = [&](int stage, int kt) {
        const uint32_t base = sb + stage * STG_BYTES;
        const int k0 = kt * BK;
#pragma unroll
        for (int h = 0; h < AT; h++) {
            const __half* asrc = Ag[h] + k0;
            const uint32_t adst = base + h * A_STG;
#pragma unroll
            for (int r = 0; r < NPASS; r++) {
                int row = a_row + r * AROWS;
                cp16(adst + (uint32_t)(row * APITCH + a_ch) * 2,
                     asrc + (size_t)row * lda + a_ch);
            }
        }
        {
            const uint32_t bdst = base + AT * A_STG;
#pragma unroll
            for (int r = 0; r < BPASS; r++) {
                int row = b_row + r * BROWS;
                cp16(bdst + (uint32_t)(row * BPITCH + b_ch) * 2,
                     Bg0 + (size_t)(k0 + row) * ldb + b_ch);
            }
        }
    };

    float c[2][2 * NJ][4];
#pragma unroll
    for (int mi = 0; mi < 2; mi++)
#pragma unroll
        for (int j = 0; j < 2 * NJ; j++)
#pragma unroll
            for (int q = 0; q < 4; q++) c[mi][j][q] = 0.0f;

#pragma unroll
    for (int s = 0; s < NST - 1; s++) {
        if (s < nk) issue(s, s);
        CP_COMMIT();
    }

    const uint32_t a_lane_off = (uint32_t)((lane & 15) * APITCH + ((lane >> 4) << 3)) * 2;
    const uint32_t b_lane_off = (uint32_t)((lane & 15) * BPITCH + ((lane >> 4) << 3)) * 2;

    for (int kt = 0; kt < nk; kt++) {
        const int kf = kt + NST - 1;
        if (kf < nk) issue(kf % NST, kf);
        CP_COMMIT();
        asm volatile("cp.async.wait_group %0;" :: "n"(NST - 1) : "memory");
        __syncthreads();

        const int stage = kt % NST;
        const uint32_t ab = sb + stage * STG_BYTES;
        const uint32_t bb = ab + AT * A_STG;

#pragma unroll
        for (int ks = 0; ks < KS; ks++) {
            uint32_t afr[AT][2][4];
            uint32_t bfr[NJ][4];
#pragma unroll
            for (int h = 0; h < AT; h++)
#pragma unroll
                for (int mi = 0; mi < 2; mi++)
                    ldsm4(afr[h][mi],
                          ab + h * A_STG + a_lane_off +
                          (uint32_t)((wm * 32 + mi * 16) * APITCH + ks * 16) * 2);
#pragma unroll
            for (int nj = 0; nj < NJ; nj++)
                ldsm4t(bfr[nj],
                       bb + b_lane_off +
                       (uint32_t)(ks * 16 * BPITCH + wn * WN + nj * 16) * 2);
#pragma unroll
            for (int mi = 0; mi < 2; mi++)
#pragma unroll
                for (int j = 0; j < 2 * NJ; j++) {
                    const int nj = j >> 1, hf = (j & 1) << 1;
                    mma16816(c[mi][j], afr[0][mi], bfr[nj][hf], bfr[nj][hf + 1]);
                    if (AT == 2)
                        mma16816(c[mi][j], afr[1][mi], bfr[nj][hf], bfr[nj][hf + 1]);
                }
        }
        __syncthreads();
    }

    // ---- epilogue ----
    const int colbase = n0 + wn * WN + (lane & 3) * 2;
    if (KHo != nullptr) {
#pragma unroll
        for (int mi = 0; mi < 2; mi++)
#pragma unroll
            for (int rr = 0; rr < 2; rr++) {
                const int row = m0 + wm * 32 + mi * 16 + (lane >> 2) + rr * 8;
                if (row >= MTOT) continue;
                const float bv = bias[row];
                if (row < 64) {
                    __half* qb = QTo + (size_t)b * HW * 64 + row;
#pragma unroll
                    for (int j = 0; j < 2 * NJ; j++) {
                        const int col = colbase + j * 8;
                        qb[(size_t)col * 64]       =
                            __float2half_rn(c[mi][j][rr * 2] + bv);
                        qb[(size_t)(col + 1) * 64] =
                            __float2half_rn(c[mi][j][rr * 2 + 1] + bv);
                    }
                } else if (row < 128) {
                    __half* ph = KHo + ((size_t)b * 64 + (row - 64)) * HW + colbase;
#pragma unroll
                    for (int j = 0; j < 2 * NJ; j++)
                        *reinterpret_cast<__half2*>(ph + j * 8) = __halves2half2(
                            __float2half_rn(c[mi][j][rr * 2] + bv),
                            __float2half_rn(c[mi][j][rr * 2 + 1] + bv));
                } else if (row < 640) {
                    __half* ph = VHo + ((size_t)b * 512 + (row - 128)) * HW + colbase;
#pragma unroll
                    for (int j = 0; j < 2 * NJ; j++)
                        *reinterpret_cast<__half2*>(ph + j * 8) = __halves2half2(
                            __float2half_rn(c[mi][j][rr * 2] + bv),
                            __float2half_rn(c[mi][j][rr * 2 + 1] + bv));
                } else {
                    float* p = C + (size_t)b * sC + (size_t)row * ldc + colbase;
#pragma unroll
                    for (int j = 0; j < 2 * NJ; j++)
                        *reinterpret_cast<float2*>(p + j * 8) =
                            make_float2(c[mi][j][rr * 2] + bv, c[mi][j][rr * 2 + 1] + bv);
                }
            }
    } else if (PEo != nullptr) {
#pragma unroll
        for (int mi = 0; mi < 2; mi++)
#pragma unroll
            for (int rr = 0; rr < 2; rr++) {
                const int rloc = wm * 32 + mi * 16 + (lane >> 2) + rr * 8;
                __half* pp = PEo + ((size_t)b * HW + m0 + rloc) * HW + colbase;
                float rsum = 0.0f;
#pragma unroll
                for (int j = 0; j < 2 * NJ; j++) {
                    float e0 = __expf(c[mi][j][rr * 2]     - 8.0f);
                    float e1 = __expf(c[mi][j][rr * 2 + 1] - 8.0f);
                    __half h0 = __float2half_rn(e0), h1 = __float2half_rn(e1);
                    *reinterpret_cast<__half2*>(pp + j * 8) = __halves2half2(h0, h1);
                    rsum += __half2float(h0) + __half2float(h1);
                }
                rsum += __shfl_xor_sync(0xffffffffu, rsum, 1);
                rsum += __shfl_xor_sync(0xffffffffu, rsum, 2);
                if ((lane & 3) == 0) sred[wn][rloc] = rsum;
            }
        __syncthreads();
        if (tid < 128) {
            float z = sred[0][tid] + sred[1][tid];
            Part[((size_t)b * gridDim.y + blockIdx.y) * HW + m0 + tid] = z;
        }
    } else {
#pragma unroll
        for (int mi = 0; mi < 2; mi++) {
            const int r0 = m0 + wm * 32 + mi * 16 + (lane >> 2);
            const float bv0 = has_bias ? bias[r0]     : 0.0f;
            const float bv1 = has_bias ? bias[r0 + 8] : 0.0f;
            float* p0 = C + (size_t)b * sC + (size_t)r0 * ldc + colbase;
            float* p1 = p0 + (size_t)8 * ldc;
            const float* q0p = Cadd ? (Cadd + (size_t)b * sC + (size_t)r0 * ldc + colbase)
                                    : nullptr;
#pragma unroll
            for (int j = 0; j < 2 * NJ; j++) {
                float2 v0 = make_float2(c[mi][j][0] + bv0, c[mi][j][1] + bv0);
                float2 v1 = make_float2(c[mi][j][2] + bv1, c[mi][j][3] + bv1);
                if (Cadd) {
                    float2 a0 = *reinterpret_cast<const float2*>(q0p + j * 8);
                    float2 a1 = *reinterpret_cast<const float2*>(q0p + (size_t)8 * ldc + j * 8);
                    v0.x += a0.x; v0.y += a0.y;
                    v1.x += a1.x; v1.y += a1.y;
                }
                *reinterpret_cast<float2*>(p0 + j * 8) = v0;
                *reinterpret_cast<float2*>(p1 + j * 8) = v1;
            }
        }
    }
}

#define SM_AT2 (3 * (2 * 128 * 40 * 2 + 32 * 136 * 2))   // 87552
#define SM_AT1 (3 * (1 * 128 * 40 * 2 + 32 * 136 * 2))   // 56832

// ---------------------------------------------------------------------------
// Z reduction + v column scaling
// ---------------------------------------------------------------------------
__global__ void zinv_k(const float* __restrict__ Part, float* __restrict__ zinv)
{
    int i = blockIdx.x * 256 + threadIdx.x;
    int b = i >> 12, r = i & 4095;
    float s = 0.0f;
#pragma unroll
    for (int jt = 0; jt < 32; jt++) s += Part[((size_t)b * 32 + jt) * HW + r];
    zinv[i] = 1.0f / s;
}

__global__ void vscale_k(__half* __restrict__ VH, const float* __restrict__ zinv)
{
    const int b = blockIdx.y;
    int idx = blockIdx.x * 256 + threadIdx.x;
    int c  = idx >> 11;
    int i2 = idx & 2047;
    __half2* p = reinterpret_cast<__half2*>(VH + ((size_t)b * 512 + c) * HW) + i2;
    float2 f = __half22float2(*p);
    float z0 = zinv[(size_t)b * HW + 2 * i2];
    float z1 = zinv[(size_t)b * HW + 2 * i2 + 1];
    *p = __floats2half2_rn(f.x * z0, f.y * z1);
}

// ---------------------------------------------------------------------------
// fp16 conversions
// ---------------------------------------------------------------------------
__global__ void tohalf4(const float* __restrict__ in, __half* __restrict__ hi,
                        int count4, size_t in_bs, size_t out_bs)
{
    size_t b = blockIdx.y;
    int i = blockIdx.x * 256 + threadIdx.x;
    if (i >= count4) return;
    float4 v = reinterpret_cast<const float4*>(in + b * in_bs)[i];
    __half2* ph = reinterpret_cast<__half2*>(hi + b * out_bs);
    ph[2 * i]     = __floats2half2_rn(v.x, v.y);
    ph[2 * i + 1] = __floats2half2_rn(v.z, v.w);
}

__global__ void splitW(const float* __restrict__ in, __half* __restrict__ hi,
                       __half* __restrict__ lo)
{
    int i = blockIdx.x * 256 + threadIdx.x;
    float v = (i < MTOT * CH) ? in[i] : 0.0f;
    __half h = __float2half_rn(v);
    hi[i] = h;
    lo[i] = __float2half_rn(v - __half2float(h));
}

// ---------------------------------------------------------------------------
// SIMT f32x2 GEMM: CY = co_w @ c_out + co_b  (no accumulate; runs on s2)
// ---------------------------------------------------------------------------
__device__ __forceinline__ unsigned long long pk2(float lo, float hi) {
    unsigned long long r;
    asm("mov.b64 %0, {%1, %2};" : "=l"(r) : "f"(lo), "f"(hi));
    return r;
}
__device__ __forceinline__ unsigned long long fma2(unsigned long long a,
                                                   unsigned long long b,
                                                   unsigned long long c) {
    unsigned long long d;
    asm("fma.rn.f32x2 %0, %1, %2, %3;" : "=l"(d) : "l"(a), "l"(b), "l"(c));
    return d;
}
__device__ __forceinline__ float2 u2f(unsigned long long u) {
    float2 f;
    asm("mov.b64 {%0, %1}, %2;" : "=f"(f.x), "=f"(f.y) : "l"(u));
    return f;
}

__global__ __launch_bounds__(256, 2)
void gemm_simt(const float* __restrict__ A, const float* __restrict__ Bm,
               const float* __restrict__ bias, float* __restrict__ Cm,
               int M, int N, int K, int lda, int ldb, int ldc,
               size_t sA, size_t sB, size_t sC)
{
    __shared__ float As[16][128 + 4];
    __shared__ float Bs[16][128];

    const int b  = blockIdx.z;
    const float* Ab = A + (size_t)b * sA;
    const float* Bb = Bm + (size_t)b * sB;
    float*       Cb = Cm + (size_t)b * sC;

    const int m0 = blockIdx.y * 128;
    const int n0 = blockIdx.x * 128;
    const int t  = threadIdx.x;
    const int tm0 = (t >> 4) << 3;
    const int tn0 = (t & 15) << 3;

    unsigned long long acc[8][4];
#pragma unroll
    for (int i = 0; i < 8; i++)
#pragma unroll
        for (int j = 0; j < 4; j++) acc[i][j] = 0ull;

    for (int k0 = 0; k0 < K; k0 += 16) {
#pragma unroll
        for (int r = 0; r < 2; r++) {
            int idx = t + r * 256;
            int row = idx >> 2;
            int c4  = (idx & 3) << 2;
            float4 v = make_float4(0.f, 0.f, 0.f, 0.f);
            if (m0 + row < M)
                v = *reinterpret_cast<const float4*>(Ab + (size_t)(m0 + row) * lda + k0 + c4);
            As[c4 + 0][row] = v.x; As[c4 + 1][row] = v.y;
            As[c4 + 2][row] = v.z; As[c4 + 3][row] = v.w;
        }
#pragma unroll
        for (int r = 0; r < 2; r++) {
            int idx = t + r * 256;
            int kr  = idx >> 5;
            int n4  = (idx & 31) << 2;
            float4 v = *reinterpret_cast<const float4*>(Bb + (size_t)(k0 + kr) * ldb + n0 + n4);
            *reinterpret_cast<float4*>(&Bs[kr][n4]) = v;
        }
        __syncthreads();
#pragma unroll
        for (int kk = 0; kk < 16; kk++) {
            float4 a0 = *reinterpret_cast<const float4*>(&As[kk][tm0]);
            float4 a1 = *reinterpret_cast<const float4*>(&As[kk][tm0 + 4]);
            ulonglong2 bl0 = *reinterpret_cast<const ulonglong2*>(&Bs[kk][tn0]);
            ulonglong2 bl1 = *reinterpret_cast<const ulonglong2*>(&Bs[kk][tn0 + 4]);
            unsigned long long bv[4] = {bl0.x, bl0.y, bl1.x, bl1.y};
            float av[8] = {a0.x, a0.y, a0.z, a0.w, a1.x, a1.y, a1.z, a1.w};
#pragma unroll
            for (int i = 0; i < 8; i++) {
                unsigned long long a2 = pk2(av[i], av[i]);
#pragma unroll
                for (int j = 0; j < 4; j++) acc[i][j] = fma2(a2, bv[j], acc[i][j]);
            }
        }
        __syncthreads();
    }
#pragma unroll
    for (int i = 0; i < 8; i++) {
        int m = m0 + tm0 + i;
        if (m >= M) continue;
        float bsv = bias[m];
        float* crow = Cb + (size_t)m * ldc + n0 + tn0;
#pragma unroll
        for (int j = 0; j < 4; j++) {
            float2 f = u2f(acc[i][j]);
            f.x += bsv; f.y += bsv;
            *reinterpret_cast<float2*>(crow + j * 2) = f;
        }
    }
}

// ---------------------------------------------------------------------------
// Channel attention kernels (fp32, small)
// ---------------------------------------------------------------------------
__global__ void chan_energy(const float* __restrict__ cq, const float* __restrict__ ck,
                            float* __restrict__ part)
{
    __shared__ float sq[64][65];
    __shared__ float sk[64][65];
    const int b = blockIdx.y;
    const int split = blockIdx.x;
    const float* cqb = cq + (size_t)b * MPAD * HW;
    const float* ckb = ck + (size_t)b * MPAD * HW;
    const int t = threadIdx.x;
    const int p0 = (t >> 4) * 4;
    const int q0 = (t & 15) * 4;

    float acc[4][4];
#pragma unroll
    for (int i = 0; i < 4; i++)
#pragma unroll
        for (int j = 0; j < 4; j++) acc[i][j] = 0.f;

    for (int c = 0; c < 4; c++) {
        const int nb = (split * 4 + c) * 64;
        __syncthreads();
#pragma unroll
        for (int i = 0; i < 16; i++) {
            int idx = t + i * 256;
            int row = idx >> 6, col = idx & 63;
            sq[row][col] = cqb[(size_t)row * HW + nb + col];
            sk[row][col] = ckb[(size_t)row * HW + nb + col];
        }
        __syncthreads();
        for (int nn = 0; nn < 64; nn++) {
            float aq[4], bk[4];
#pragma unroll
            for (int i = 0; i < 4; i++) aq[i] = sq[p0 + i][nn];
#pragma unroll
            for (int j = 0; j < 4; j++) bk[j] = sk[q0 + j][nn];
#pragma unroll
            for (int i = 0; i < 4; i++)
#pragma unroll
                for (int j = 0; j < 4; j++) acc[i][j] += aq[i] * bk[j];
        }
    }
    float* out = part + (size_t)split * (BATCH * 4096) + (size_t)b * 4096;
#pragma unroll
    for (int i = 0; i < 4; i++)
#pragma unroll
        for (int j = 0; j < 4; j++)
            out[(p0 + i) * 64 + (q0 + j)] = acc[i][j];
}

__global__ void reduce_ce(const float* __restrict__ part, float* __restrict__ cE)
{
    int i = blockIdx.x * 256 + threadIdx.x;
    float s = 0.f;
#pragma unroll
    for (int k = 0; k < 16; k++) s += part[(size_t)k * (BATCH * 4096) + i];
    cE[i] = s;
}

__global__ void chan_softmax(float* __restrict__ cE)
{
    __shared__ float red[64];
    const int row = blockIdx.x;
    float* rp = cE + (size_t)row * 64;
    const int t = threadIdx.x;
    float v = rp[t];
    red[t] = v; __syncthreads();
    for (int s = 32; s > 0; s >>= 1) {
        if (t < s) red[t] = fmaxf(red[t], red[t + s]);
        __syncthreads();
    }
    float m = red[0]; __syncthreads();
    float e = __expf(v - m);
    red[t] = e; __syncthreads();
    for (int s = 32; s > 0; s >>= 1) {
        if (t < s) red[t] += red[t + s];
        __syncthreads();
    }
    rp[t] = e / red[0];
}

__global__ void chan_out(const float* __restrict__ cattn, const float* __restrict__ cv,
                         float* __restrict__ cout)
{
    __shared__ float sa[4096];
    const int b = blockIdx.y;
    const int n = blockIdx.x * 256 + threadIdx.x;
    const float* at = cattn + (size_t)b * 4096;
    for (int i = threadIdx.x; i < 4096; i += 256) sa[i] = at[i];
    __syncthreads();

    const float* cvb = cv + (size_t)b * MPAD * HW;
    float acc[64];
#pragma unroll
    for (int p = 0; p < 64; p++) acc[p] = 0.f;
    for (int q = 0; q < 64; q++) {
        float vv = cvb[(size_t)q * HW + n];
#pragma unroll
        for (int p = 0; p < 64; p++) acc[p] += sa[p * 64 + q] * vv;
    }
    float* ob = cout + (size_t)b * CQD * HW;
#pragma unroll
    for (int p = 0; p < 64; p++) ob[(size_t)p * HW + n] = acc[p];
}

// ---------------------------------------------------------------------------
// Launch: channel path INCLUDING final projection runs on s2; K4 fuses +CY.
// ---------------------------------------------------------------------------
extern "C" void kernel_launch(void* const* d_in, const int* in_sizes, int n_in,
                              void* d_out, int out_size)
{
    (void)in_sizes; (void)n_in; (void)out_size;

    static cudaStream_t s2 = nullptr;
    static cudaEvent_t evFork = nullptr, evJoin = nullptr;
    if (s2 == nullptr) {
        cudaStreamCreateWithFlags(&s2, cudaStreamNonBlocking);
        cudaEventCreateWithFlags(&evFork, cudaEventDisableTiming);
        cudaEventCreateWithFlags(&evJoin, cudaEventDisableTiming);
    }

    const float* x = (const float*)d_in[0];

    float* S = nullptr;
    cudaGetSymbolAddress((void**)&S, g_scratch);

    float* W    = S + OFF_W;
    float* BI   = S + OFF_BI;
    float* Y    = S + OFF_Y;
    float* PART = S + OFF_PART;
    float* ZINV = S + OFF_ZINV;
    float* CE   = S + OFF_CE;
    float* CEP  = S + OFF_CEP;
    float* CO   = S + OFF_CO;
    float* CY   = S + OFF_CY;
    float* out  = (float*)d_out;

    __half* WH  = (__half*)(S + OFF_WH);
    __half* WL  = (__half*)(S + OFF_WL);
    __half* XH  = (__half*)(S + OFF_XH);
    __half* QTH = (__half*)(S + OFF_QTH);
    __half* KH  = (__half*)(S + OFF_KH);
    __half* VH  = (__half*)(S + OFF_VH);
    __half* PH  = (__half*)(S + OFF_PH);

    // pack fp32 weights + bias
    cudaMemcpyAsync(W +      0, d_in[1],  64  * 512 * sizeof(float), cudaMemcpyDeviceToDevice);
    cudaMemcpyAsync(W +  32768, d_in[3],  64  * 512 * sizeof(float), cudaMemcpyDeviceToDevice);
    cudaMemcpyAsync(W +  65536, d_in[5],  512 * 512 * sizeof(float), cudaMemcpyDeviceToDevice);
    cudaMemcpyAsync(W + 327680, d_in[7],  64  * 512 * sizeof(float), cudaMemcpyDeviceToDevice);
    cudaMemcpyAsync(W + 360448, d_in[9],  64  * 512 * sizeof(float), cudaMemcpyDeviceToDevice);
    cudaMemcpyAsync(W + 393216, d_in[11], 64  * 512 * sizeof(float), cudaMemcpyDeviceToDevice);
    cudaMemcpyAsync(BI +   0, d_in[2],  64  * sizeof(float), cudaMemcpyDeviceToDevice);
    cudaMemcpyAsync(BI +  64, d_in[4],  64  * sizeof(float), cudaMemcpyDeviceToDevice);
    cudaMemcpyAsync(BI + 128, d_in[6],  512 * sizeof(float), cudaMemcpyDeviceToDevice);
    cudaMemcpyAsync(BI + 640, d_in[8],  64  * sizeof(float), cudaMemcpyDeviceToDevice);
    cudaMemcpyAsync(BI + 704, d_in[10], 64  * sizeof(float), cudaMemcpyDeviceToDevice);
    cudaMemcpyAsync(BI + 768, d_in[12], 64  * sizeof(float), cudaMemcpyDeviceToDevice);

    cudaFuncSetAttribute((const void*)gemm_mma<2, 32, 3, 128, 2>,
                         cudaFuncAttributeMaxDynamicSharedMemorySize, SM_AT2);
    cudaFuncSetAttribute((const void*)gemm_mma<1, 32, 3, 128, 2>,
                         cudaFuncAttributeMaxDynamicSharedMemorySize, SM_AT1);

    // fp16 conversions: W split, x single
    splitW<<<(MPAD * CH + 255) / 256, 256>>>(W, WH, WL);
    tohalf4<<<dim3(2048, BATCH), 256>>>(x, XH, 524288, (size_t)CH * HW, (size_t)CH * HW);

    // K1: projections (2-term), routed epilogue
    gemm_mma<2, 32, 3, 128, 2><<<dim3(7, 32, BATCH), 256, SM_AT2>>>(
        WH, WL, XH, BI, Y, 512, 512, HW, HW,
        (size_t)0, (size_t)CH * HW, (size_t)MPAD * HW, 1, QTH, KH, VH,
        nullptr, nullptr, nullptr);

    // ---- fork: full channel path on s2 (incl. final co_w projection) ----
    cudaEventRecord(evFork, 0);
    cudaStreamWaitEvent(s2, evFork, 0);

    chan_energy<<<dim3(16, BATCH), 256, 0, s2>>>(
        Y + (size_t)640 * HW, Y + (size_t)704 * HW, CEP);
    reduce_ce<<<128, 256, 0, s2>>>(CEP, CE);
    chan_softmax<<<BATCH * 64, 64, 0, s2>>>(CE);
    chan_out<<<dim3(16, BATCH), 256, 0, s2>>>(CE, Y + (size_t)768 * HW, CO);
    // CY = co_w @ c_out + co_b
    gemm_simt<<<dim3(32, 4, BATCH), 256, 0, s2>>>(
        (const float*)d_in[13], CO, (const float*)d_in[14], CY,
        CH, HW, CQD, CQD, HW, HW,
        (size_t)0, (size_t)CQD * HW, (size_t)CH * HW);
    cudaEventRecord(evJoin, s2);

    // ---- main stream: position path ----
    gemm_mma<1, 32, 3, 128, 2><<<dim3(32, 32, BATCH), 256, SM_AT1>>>(
        QTH, nullptr, KH, nullptr, nullptr, 64, 64, HW, 0,
        (size_t)HW * 64, (size_t)64 * HW, (size_t)0, 0,
        nullptr, nullptr, nullptr, PH, PART, nullptr);

    zinv_k<<<BATCH * HW / 256, 256>>>(PART, ZINV);
    vscale_k<<<dim3(4096, BATCH), 256>>>(VH, ZINV);

    // ---- join BEFORE K4: its epilogue reads CY ----
    cudaStreamWaitEvent(0, evJoin, 0);

    // K4: out = vscaled @ PE + CY  (fused final add)
    gemm_mma<1, 32, 3, 128, 2><<<dim3(4, 32, BATCH), 256, SM_AT1>>>(
        VH, nullptr, PH, nullptr, out, HW, HW, HW, HW,
        (size_t)CH * HW, (size_t)HW * HW, (size_t)CH * HW, 0,
        nullptr, nullptr, nullptr, nullptr, nullptr, CY);
}

// round 15
// speedup vs baseline: 1.1778x; 1.0650x over previous
#include <cuda_runtime.h>
#include <cuda_fp16.h>
#include <cstdint>
#include <cstddef>

// ---------------------------------------------------------------------------
// Problem constants
// ---------------------------------------------------------------------------
#define BATCH 8
#define CH    512
#define CQD   64
#define HW    4096
#define MTOT  832
#define MPAD  896

// scratch layout (float offsets)
#define OFF_BI   425984u
#define OFF_WH   427008u
#define OFF_WL   656384u
#define OFF_XH   885760u
#define OFF_Y    17662976u
#define OFF_QTH  47023104u
#define OFF_KH   49120256u
#define OFF_VH   51217408u
#define OFF_PH   59606016u
#define OFF_PART 126714880u
#define OFF_ZINV 127763456u
#define OFF_CE   127796224u
#define OFF_CEP  127828992u
#define OFF_CO   128353280u
#define SCRATCH_FLOATS 130450432u

__device__ float g_scratch[SCRATCH_FLOATS];

// ---------------------------------------------------------------------------
// PTX helpers
// ---------------------------------------------------------------------------
__device__ __forceinline__ uint32_t smem_to_u32(const void* p) {
    uint32_t a;
    asm("{ .reg .u64 t; cvta.to.shared.u64 t, %1; cvt.u32.u64 %0, t; }" : "=r"(a) : "l"(p));
    return a;
}

__device__ __forceinline__ void ldsm4(uint32_t* r, uint32_t addr) {
    asm volatile("ldmatrix.sync.aligned.m8n8.x4.shared.b16 {%0,%1,%2,%3}, [%4];"
                 : "=r"(r[0]), "=r"(r[1]), "=r"(r[2]), "=r"(r[3]) : "r"(addr));
}
__device__ __forceinline__ void ldsm4t(uint32_t* r, uint32_t addr) {
    asm volatile("ldmatrix.sync.aligned.m8n8.x4.trans.shared.b16 {%0,%1,%2,%3}, [%4];"
                 : "=r"(r[0]), "=r"(r[1]), "=r"(r[2]), "=r"(r[3]) : "r"(addr));
}
__device__ __forceinline__ void mma16816(float* c, const uint32_t* a,
                                         uint32_t b0, uint32_t b1) {
    asm volatile("mma.sync.aligned.m16n8k16.row.col.f32.f16.f16.f32 "
                 "{%0,%1,%2,%3}, {%4,%5,%6,%7}, {%8,%9}, {%0,%1,%2,%3};"
                 : "+f"(c[0]), "+f"(c[1]), "+f"(c[2]), "+f"(c[3])
                 : "r"(a[0]), "r"(a[1]), "r"(a[2]), "r"(a[3]), "r"(b0), "r"(b1));
}
__device__ __forceinline__ void cp16(uint32_t dst, const void* src) {
    asm volatile("cp.async.cg.shared.global [%0], [%1], 16;" :: "r"(dst), "l"(src));
}
#define CP_COMMIT() asm volatile("cp.async.commit_group;" ::: "memory")

// ---------------------------------------------------------------------------
// fp16-split GEMM via mma.sync (HMMA) — proven R8/R12 config.
// Epilogue modes:
//   KHo != nullptr : K1 routed projection epilogue
//   PEo != nullptr : K2 exp epilogue (PE fp16 + row-sum partials)
//   else           : fp32 C (+bias)
// ---------------------------------------------------------------------------
template<int AT, int BK, int NST, int BN, int OCC>
__global__ void __launch_bounds__(256, OCC) gemm_mma(
    const __half* __restrict__ Ah, const __half* __restrict__ Al,
    const __half* __restrict__ Bh,
    const float* __restrict__ bias, float* __restrict__ C,
    int K, int lda, int ldb, int ldc,
    size_t sA, size_t sB, size_t sC, int has_bias,
    __half* __restrict__ QTo, __half* __restrict__ KHo, __half* __restrict__ VHo,
    __half* __restrict__ PEo, float* __restrict__ Part)
{
    constexpr int APITCH = BK + 8;
    constexpr int BPITCH = BN + 8;
    constexpr int A_STG  = 128 * APITCH * 2;
    constexpr int B_STG  = BK * BPITCH * 2;
    constexpr int STG_BYTES = AT * A_STG + B_STG;
    constexpr int ATPR  = BK / 8;
    constexpr int AROWS = 256 / ATPR;
    constexpr int NPASS = 128 / AROWS;
    constexpr int BTPR  = BN / 8;
    constexpr int BROWS = 256 / BTPR;
    constexpr int BPASS = BK / BROWS;
    constexpr int KS    = BK / 16;
    constexpr int NJ    = BN / 32;
    constexpr int WN    = BN / 2;

    extern __shared__ char smem[];
    __shared__ float sred[2][128];
    const uint32_t sb = smem_to_u32(smem);
    const int tid  = threadIdx.x;
    const int w    = tid >> 5, lane = tid & 31;
    const int wm   = w & 3,    wn   = w >> 2;
    const int b    = blockIdx.z;
    const int m0   = blockIdx.x * 128, n0 = blockIdx.y * BN;

    const __half* Ag[AT];
    Ag[0] = Ah + (size_t)b * sA + (size_t)m0 * lda;
    if (AT == 2) Ag[1] = Al + (size_t)b * sA + (size_t)m0 * lda;
    const __half* Bg0 = Bh + (size_t)b * sB + n0;

    const int nk = K / BK;

    const int a_row = tid / ATPR, a_ch = (tid % ATPR) << 3;
    const int b_row = tid / BTPR, b_ch = (tid % BTPR) << 3;

    auto issue = [&](int stage, int kt) {
        const uint32_t base = sb + stage * STG_BYTES;
        const int k0 = kt * BK;
#pragma unroll
        for (int h = 0; h < AT; h++) {
            const __half* asrc = Ag[h] + k0;
            const uint32_t adst = base + h * A_STG;
#pragma unroll
            for (int r = 0; r < NPASS; r++) {
                int row = a_row + r * AROWS;
                cp16(adst + (uint32_t)(row * APITCH + a_ch) * 2,
                     asrc + (size_t)row * lda + a_ch);
            }
        }
        {
            const uint32_t bdst = base + AT * A_STG;
#pragma unroll
            for (int r = 0; r < BPASS; r++) {
                int row = b_row + r * BROWS;
                cp16(bdst + (uint32_t)(row * BPITCH + b_ch) * 2,
                     Bg0 + (size_t)(k0 + row) * ldb + b_ch);
            }
        }
    };

    float c[2][2 * NJ][4];
#pragma unroll
    for (int mi = 0; mi < 2; mi++)
#pragma unroll
        for (int j = 0; j < 2 * NJ; j++)
#pragma unroll
            for (int q = 0; q < 4; q++) c[mi][j][q] = 0.0f;

#pragma unroll
    for (int s = 0; s < NST - 1; s++) {
        if (s < nk) issue(s, s);
        CP_COMMIT();
    }

    const uint32_t a_lane_off = (uint32_t)((lane & 15) * APITCH + ((lane >> 4) << 3)) * 2;
    const uint32_t b_lane_off = (uint32_t)((lane & 15) * BPITCH + ((lane >> 4) << 3)) * 2;

    for (int kt = 0; kt < nk; kt++) {
        const int kf = kt + NST - 1;
        if (kf < nk) issue(kf % NST, kf);
        CP_COMMIT();
        asm volatile("cp.async.wait_group %0;" :: "n"(NST - 1) : "memory");
        __syncthreads();

        const int stage = kt % NST;
        const uint32_t ab = sb + stage * STG_BYTES;
        const uint32_t bb = ab + AT * A_STG;

#pragma unroll
        for (int ks = 0; ks < KS; ks++) {
            uint32_t afr[AT][2][4];
            uint32_t bfr[NJ][4];
#pragma unroll
            for (int h = 0; h < AT; h++)
#pragma unroll
                for (int mi = 0; mi < 2; mi++)
                    ldsm4(afr[h][mi],
                          ab + h * A_STG + a_lane_off +
                          (uint32_t)((wm * 32 + mi * 16) * APITCH + ks * 16) * 2);
#pragma unroll
            for (int nj = 0; nj < NJ; nj++)
                ldsm4t(bfr[nj],
                       bb + b_lane_off +
                       (uint32_t)(ks * 16 * BPITCH + wn * WN + nj * 16) * 2);
#pragma unroll
            for (int mi = 0; mi < 2; mi++)
#pragma unroll
                for (int j = 0; j < 2 * NJ; j++) {
                    const int nj = j >> 1, hf = (j & 1) << 1;
                    mma16816(c[mi][j], afr[0][mi], bfr[nj][hf], bfr[nj][hf + 1]);
                    if (AT == 2)
                        mma16816(c[mi][j], afr[1][mi], bfr[nj][hf], bfr[nj][hf + 1]);
                }
        }
        __syncthreads();
    }

    // ---- epilogue ----
    const int colbase = n0 + wn * WN + (lane & 3) * 2;
    if (KHo != nullptr) {
#pragma unroll
        for (int mi = 0; mi < 2; mi++)
#pragma unroll
            for (int rr = 0; rr < 2; rr++) {
                const int row = m0 + wm * 32 + mi * 16 + (lane >> 2) + rr * 8;
                if (row >= MTOT) continue;
                const float bv = bias[row];
                if (row < 64) {
                    __half* qb = QTo + (size_t)b * HW * 64 + row;
#pragma unroll
                    for (int j = 0; j < 2 * NJ; j++) {
                        const int col = colbase + j * 8;
                        qb[(size_t)col * 64]       =
                            __float2half_rn(c[mi][j][rr * 2] + bv);
                        qb[(size_t)(col + 1) * 64] =
                            __float2half_rn(c[mi][j][rr * 2 + 1] + bv);
                    }
                } else if (row < 128) {
                    __half* ph = KHo + ((size_t)b * 64 + (row - 64)) * HW + colbase;
#pragma unroll
                    for (int j = 0; j < 2 * NJ; j++)
                        *reinterpret_cast<__half2*>(ph + j * 8) = __halves2half2(
                            __float2half_rn(c[mi][j][rr * 2] + bv),
                            __float2half_rn(c[mi][j][rr * 2 + 1] + bv));
                } else if (row < 640) {
                    __half* ph = VHo + ((size_t)b * 512 + (row - 128)) * HW + colbase;
#pragma unroll
                    for (int j = 0; j < 2 * NJ; j++)
                        *reinterpret_cast<__half2*>(ph + j * 8) = __halves2half2(
                            __float2half_rn(c[mi][j][rr * 2] + bv),
                            __float2half_rn(c[mi][j][rr * 2 + 1] + bv));
                } else {
                    float* p = C + (size_t)b * sC + (size_t)row * ldc + colbase;
#pragma unroll
                    for (int j = 0; j < 2 * NJ; j++)
                        *reinterpret_cast<float2*>(p + j * 8) =
                            make_float2(c[mi][j][rr * 2] + bv, c[mi][j][rr * 2 + 1] + bv);
                }
            }
    } else if (PEo != nullptr) {
#pragma unroll
        for (int mi = 0; mi < 2; mi++)
#pragma unroll
            for (int rr = 0; rr < 2; rr++) {
                const int rloc = wm * 32 + mi * 16 + (lane >> 2) + rr * 8;
                __half* pp = PEo + ((size_t)b * HW + m0 + rloc) * HW + colbase;
                float rsum = 0.0f;
#pragma unroll
                for (int j = 0; j < 2 * NJ; j++) {
                    float e0 = __expf(c[mi][j][rr * 2]     - 8.0f);
                    float e1 = __expf(c[mi][j][rr * 2 + 1] - 8.0f);
                    __half h0 = __float2half_rn(e0), h1 = __float2half_rn(e1);
                    *reinterpret_cast<__half2*>(pp + j * 8) = __halves2half2(h0, h1);
                    rsum += __half2float(h0) + __half2float(h1);
                }
                rsum += __shfl_xor_sync(0xffffffffu, rsum, 1);
                rsum += __shfl_xor_sync(0xffffffffu, rsum, 2);
                if ((lane & 3) == 0) sred[wn][rloc] = rsum;
            }
        __syncthreads();
        if (tid < 128) {
            float z = sred[0][tid] + sred[1][tid];
            Part[((size_t)b * gridDim.y + blockIdx.y) * HW + m0 + tid] = z;
        }
    } else {
#pragma unroll
        for (int mi = 0; mi < 2; mi++) {
            const int r0 = m0 + wm * 32 + mi * 16 + (lane >> 2);
            const float bv0 = has_bias ? bias[r0]     : 0.0f;
            const float bv1 = has_bias ? bias[r0 + 8] : 0.0f;
            float* p0 = C + (size_t)b * sC + (size_t)r0 * ldc + colbase;
            float* p1 = p0 + (size_t)8 * ldc;
#pragma unroll
            for (int j = 0; j < 2 * NJ; j++) {
                *reinterpret_cast<float2*>(p0 + j * 8) =
                    make_float2(c[mi][j][0] + bv0, c[mi][j][1] + bv0);
                *reinterpret_cast<float2*>(p1 + j * 8) =
                    make_float2(c[mi][j][2] + bv1, c[mi][j][3] + bv1);
            }
        }
    }
}

#define SM_AT2 (3 * (2 * 128 * 40 * 2 + 32 * 136 * 2))   // 87552
#define SM_AT1 (3 * (1 * 128 * 40 * 2 + 32 * 136 * 2))   // 56832

// ---------------------------------------------------------------------------
// Z reduction + v column scaling
// ---------------------------------------------------------------------------
__global__ void zinv_k(const float* __restrict__ Part, float* __restrict__ zinv)
{
    int i = blockIdx.x * 256 + threadIdx.x;
    int b = i >> 12, r = i & 4095;
    float s = 0.0f;
#pragma unroll
    for (int jt = 0; jt < 32; jt++) s += Part[((size_t)b * 32 + jt) * HW + r];
    zinv[i] = 1.0f / s;
}

__global__ void vscale_k(__half* __restrict__ VH, const float* __restrict__ zinv)
{
    const int b = blockIdx.y;
    int idx = blockIdx.x * 256 + threadIdx.x;
    int c  = idx >> 11;
    int i2 = idx & 2047;
    __half2* p = reinterpret_cast<__half2*>(VH + ((size_t)b * 512 + c) * HW) + i2;
    float2 f = __half22float2(*p);
    float z0 = zinv[(size_t)b * HW + 2 * i2];
    float z1 = zinv[(size_t)b * HW + 2 * i2 + 1];
    *p = __floats2half2_rn(f.x * z0, f.y * z1);
}

// ---------------------------------------------------------------------------
// fp16 conversions (direct-from-input weight/bias packing)
// ---------------------------------------------------------------------------
__global__ void tohalf4(const float* __restrict__ in, __half* __restrict__ hi,
                        int count4, size_t in_bs, size_t out_bs)
{
    size_t b = blockIdx.y;
    int i = blockIdx.x * 256 + threadIdx.x;
    if (i >= count4) return;
    float4 v = reinterpret_cast<const float4*>(in + b * in_bs)[i];
    __half2* ph = reinterpret_cast<__half2*>(hi + b * out_bs);
    ph[2 * i]     = __floats2half2_rn(v.x, v.y);
    ph[2 * i + 1] = __floats2half2_rn(v.z, v.w);
}

// splits the six projection weight matrices directly from their input
// pointers into the packed WH/WL layout (rows: pq 0-63, pk 64-127,
// pv 128-639, cq 640-703, ck 704-767, cv 768-831, zero >= 832)
__global__ void splitW6(const float* __restrict__ pq, const float* __restrict__ pk,
                        const float* __restrict__ pv, const float* __restrict__ cq,
                        const float* __restrict__ ck, const float* __restrict__ cv,
                        __half* __restrict__ hi, __half* __restrict__ lo)
{
    int i = blockIdx.x * 256 + threadIdx.x;     // 0 .. MPAD*CH-1
    int row = i >> 9;
    int col = i & 511;
    float v = 0.0f;
    if (row < 64)        v = pq[(size_t)row * 512 + col];
    else if (row < 128)  v = pk[(size_t)(row - 64) * 512 + col];
    else if (row < 640)  v = pv[(size_t)(row - 128) * 512 + col];
    else if (row < 704)  v = cq[(size_t)(row - 640) * 512 + col];
    else if (row < 768)  v = ck[(size_t)(row - 704) * 512 + col];
    else if (row < 832)  v = cv[(size_t)(row - 768) * 512 + col];
    __half h = __float2half_rn(v);
    hi[i] = h;
    lo[i] = __float2half_rn(v - __half2float(h));
}

// gathers the six bias vectors into packed BI
__global__ void bias_pack(const float* __restrict__ pq, const float* __restrict__ pk,
                          const float* __restrict__ pv, const float* __restrict__ cq,
                          const float* __restrict__ ck, const float* __restrict__ cv,
                          float* __restrict__ BI)
{
    int i = blockIdx.x * 128 + threadIdx.x;     // 0 .. MPAD-1
    if (i >= MPAD) return;
    float v = 0.0f;
    if (i < 64)        v = pq[i];
    else if (i < 128)  v = pk[i - 64];
    else if (i < 640)  v = pv[i - 128];
    else if (i < 704)  v = cq[i - 640];
    else if (i < 768)  v = ck[i - 704];
    else if (i < 832)  v = cv[i - 768];
    BI[i] = v;
}

// ---------------------------------------------------------------------------
// SIMT f32x2 GEMM (small K8 accumulate)
// ---------------------------------------------------------------------------
__device__ __forceinline__ unsigned long long pk2(float lo, float hi) {
    unsigned long long r;
    asm("mov.b64 %0, {%1, %2};" : "=l"(r) : "f"(lo), "f"(hi));
    return r;
}
__device__ __forceinline__ unsigned long long fma2(unsigned long long a,
                                                   unsigned long long b,
                                                   unsigned long long c) {
    unsigned long long d;
    asm("fma.rn.f32x2 %0, %1, %2, %3;" : "=l"(d) : "l"(a), "l"(b), "l"(c));
    return d;
}
__device__ __forceinline__ float2 u2f(unsigned long long u) {
    float2 f;
    asm("mov.b64 {%0, %1}, %2;" : "=f"(f.x), "=f"(f.y) : "l"(u));
    return f;
}

__global__ __launch_bounds__(256, 2)
void gemm_acc(const float* __restrict__ A, const float* __restrict__ Bm,
              const float* __restrict__ bias, float* __restrict__ Cm,
              int M, int N, int K, int lda, int ldb, int ldc,
              size_t sA, size_t sB, size_t sC)
{
    __shared__ float As[16][128 + 4];
    __shared__ float Bs[16][128];

    const int b  = blockIdx.z;
    const float* Ab = A + (size_t)b * sA;
    const float* Bb = Bm + (size_t)b * sB;
    float*       Cb = Cm + (size_t)b * sC;

    const int m0 = blockIdx.y * 128;
    const int n0 = blockIdx.x * 128;
    const int t  = threadIdx.x;
    const int tm0 = (t >> 4) << 3;
    const int tn0 = (t & 15) << 3;

    unsigned long long acc[8][4];
#pragma unroll
    for (int i = 0; i < 8; i++)
#pragma unroll
        for (int j = 0; j < 4; j++) acc[i][j] = 0ull;

    for (int k0 = 0; k0 < K; k0 += 16) {
#pragma unroll
        for (int r = 0; r < 2; r++) {
            int idx = t + r * 256;
            int row = idx >> 2;
            int c4  = (idx & 3) << 2;
            float4 v = make_float4(0.f, 0.f, 0.f, 0.f);
            if (m0 + row < M)
                v = *reinterpret_cast<const float4*>(Ab + (size_t)(m0 + row) * lda + k0 + c4);
            As[c4 + 0][row] = v.x; As[c4 + 1][row] = v.y;
            As[c4 + 2][row] = v.z; As[c4 + 3][row] = v.w;
        }
#pragma unroll
        for (int r = 0; r < 2; r++) {
            int idx = t + r * 256;
            int kr  = idx >> 5;
            int n4  = (idx & 31) << 2;
            float4 v = *reinterpret_cast<const float4*>(Bb + (size_t)(k0 + kr) * ldb + n0 + n4);
            *reinterpret_cast<float4*>(&Bs[kr][n4]) = v;
        }
        __syncthreads();
#pragma unroll
        for (int kk = 0; kk < 16; kk++) {
            float4 a0 = *reinterpret_cast<const float4*>(&As[kk][tm0]);
            float4 a1 = *reinterpret_cast<const float4*>(&As[kk][tm0 + 4]);
            ulonglong2 bl0 = *reinterpret_cast<const ulonglong2*>(&Bs[kk][tn0]);
            ulonglong2 bl1 = *reinterpret_cast<const ulonglong2*>(&Bs[kk][tn0 + 4]);
            unsigned long long bv[4] = {bl0.x, bl0.y, bl1.x, bl1.y};
            float av[8] = {a0.x, a0.y, a0.z, a0.w, a1.x, a1.y, a1.z, a1.w};
#pragma unroll
            for (int i = 0; i < 8; i++) {
                unsigned long long a2 = pk2(av[i], av[i]);
#pragma unroll
                for (int j = 0; j < 4; j++) acc[i][j] = fma2(a2, bv[j], acc[i][j]);
            }
        }
        __syncthreads();
    }
#pragma unroll
    for (int i = 0; i < 8; i++) {
        int m = m0 + tm0 + i;
        if (m >= M) continue;
        float bsv = bias[m];
        float* crow = Cb + (size_t)m * ldc + n0 + tn0;
#pragma unroll
        for (int j = 0; j < 4; j++) {
            float2 f = u2f(acc[i][j]);
            float2 o = *reinterpret_cast<const float2*>(crow + j * 2);
            f.x += bsv + o.x; f.y += bsv + o.y;
            *reinterpret_cast<float2*>(crow + j * 2) = f;
        }
    }
}

// ---------------------------------------------------------------------------
// Channel attention kernels (fp32, small)
// ---------------------------------------------------------------------------
__global__ void chan_energy(const float* __restrict__ cq, const float* __restrict__ ck,
                            float* __restrict__ part)
{
    __shared__ float sq[64][65];
    __shared__ float sk[64][65];
    const int b = blockIdx.y;
    const int split = blockIdx.x;
    const float* cqb = cq + (size_t)b * MPAD * HW;
    const float* ckb = ck + (size_t)b * MPAD * HW;
    const int t = threadIdx.x;
    const int p0 = (t >> 4) * 4;
    const int q0 = (t & 15) * 4;

    float acc[4][4];
#pragma unroll
    for (int i = 0; i < 4; i++)
#pragma unroll
        for (int j = 0; j < 4; j++) acc[i][j] = 0.f;

    for (int c = 0; c < 4; c++) {
        const int nb = (split * 4 + c) * 64;
        __syncthreads();
#pragma unroll
        for (int i = 0; i < 16; i++) {
            int idx = t + i * 256;
            int row = idx >> 6, col = idx & 63;
            sq[row][col] = cqb[(size_t)row * HW + nb + col];
            sk[row][col] = ckb[(size_t)row * HW + nb + col];
        }
        __syncthreads();
        for (int nn = 0; nn < 64; nn++) {
            float aq[4], bk[4];
#pragma unroll
            for (int i = 0; i < 4; i++) aq[i] = sq[p0 + i][nn];
#pragma unroll
            for (int j = 0; j < 4; j++) bk[j] = sk[q0 + j][nn];
#pragma unroll
            for (int i = 0; i < 4; i++)
#pragma unroll
                for (int j = 0; j < 4; j++) acc[i][j] += aq[i] * bk[j];
        }
    }
    float* out = part + (size_t)split * (BATCH * 4096) + (size_t)b * 4096;
#pragma unroll
    for (int i = 0; i < 4; i++)
#pragma unroll
        for (int j = 0; j < 4; j++)
            out[(p0 + i) * 64 + (q0 + j)] = acc[i][j];
}

__global__ void reduce_ce(const float* __restrict__ part, float* __restrict__ cE)
{
    int i = blockIdx.x * 256 + threadIdx.x;
    float s = 0.f;
#pragma unroll
    for (int k = 0; k < 16; k++) s += part[(size_t)k * (BATCH * 4096) + i];
    cE[i] = s;
}

__global__ void chan_softmax(float* __restrict__ cE)
{
    __shared__ float red[64];
    const int row = blockIdx.x;
    float* rp = cE + (size_t)row * 64;
    const int t = threadIdx.x;
    float v = rp[t];
    red[t] = v; __syncthreads();
    for (int s = 32; s > 0; s >>= 1) {
        if (t < s) red[t] = fmaxf(red[t], red[t + s]);
        __syncthreads();
    }
    float m = red[0]; __syncthreads();
    float e = __expf(v - m);
    red[t] = e; __syncthreads();
    for (int s = 32; s > 0; s >>= 1) {
        if (t < s) red[t] += red[t + s];
        __syncthreads();
    }
    rp[t] = e / red[0];
}

__global__ void chan_out(const float* __restrict__ cattn, const float* __restrict__ cv,
                         float* __restrict__ cout)
{
    __shared__ float sa[4096];
    const int b = blockIdx.y;
    const int n = blockIdx.x * 256 + threadIdx.x;
    const float* at = cattn + (size_t)b * 4096;
    for (int i = threadIdx.x; i < 4096; i += 256) sa[i] = at[i];
    __syncthreads();

    const float* cvb = cv + (size_t)b * MPAD * HW;
    float acc[64];
#pragma unroll
    for (int p = 0; p < 64; p++) acc[p] = 0.f;
    for (int q = 0; q < 64; q++) {
        float vv = cvb[(size_t)q * HW + n];
#pragma unroll
        for (int p = 0; p < 64; p++) acc[p] += sa[p * 64 + q] * vv;
    }
    float* ob = cout + (size_t)b * CQD * HW;
#pragma unroll
    for (int p = 0; p < 64; p++) ob[(size_t)p * HW + n] = acc[p];
}

// ---------------------------------------------------------------------------
// Launch (two-stream fork/join: channel path overlaps K2/K4)
// ---------------------------------------------------------------------------
extern "C" void kernel_launch(void* const* d_in, const int* in_sizes, int n_in,
                              void* d_out, int out_size)
{
    (void)in_sizes; (void)n_in; (void)out_size;

    static cudaStream_t s2 = nullptr;
    static cudaEvent_t evFork = nullptr, evJoin = nullptr;
    if (s2 == nullptr) {
        cudaStreamCreateWithFlags(&s2, cudaStreamNonBlocking);
        cudaEventCreateWithFlags(&evFork, cudaEventDisableTiming);
        cudaEventCreateWithFlags(&evJoin, cudaEventDisableTiming);
    }

    const float* x = (const float*)d_in[0];

    float* S = nullptr;
    cudaGetSymbolAddress((void**)&S, g_scratch);

    float* BI   = S + OFF_BI;
    float* Y    = S + OFF_Y;
    float* PART = S + OFF_PART;
    float* ZINV = S + OFF_ZINV;
    float* CE   = S + OFF_CE;
    float* CEP  = S + OFF_CEP;
    float* CO   = S + OFF_CO;
    float* out  = (float*)d_out;

    __half* WH  = (__half*)(S + OFF_WH);
    __half* WL  = (__half*)(S + OFF_WL);
    __half* XH  = (__half*)(S + OFF_XH);
    __half* QTH = (__half*)(S + OFF_QTH);
    __half* KH  = (__half*)(S + OFF_KH);
    __half* VH  = (__half*)(S + OFF_VH);
    __half* PH  = (__half*)(S + OFF_PH);

    cudaFuncSetAttribute((const void*)gemm_mma<2, 32, 3, 128, 2>,
                         cudaFuncAttributeMaxDynamicSharedMemorySize, SM_AT2);
    cudaFuncSetAttribute((const void*)gemm_mma<1, 32, 3, 128, 2>,
                         cudaFuncAttributeMaxDynamicSharedMemorySize, SM_AT1);

    // direct weight/bias packing + x conversion (no memcpy preamble)
    splitW6<<<(MPAD * CH + 255) / 256, 256>>>(
        (const float*)d_in[1], (const float*)d_in[3], (const float*)d_in[5],
        (const float*)d_in[7], (const float*)d_in[9], (const float*)d_in[11],
        WH, WL);
    bias_pack<<<(MPAD + 127) / 128, 128>>>(
        (const float*)d_in[2], (const float*)d_in[4], (const float*)d_in[6],
        (const float*)d_in[8], (const float*)d_in[10], (const float*)d_in[12],
        BI);
    tohalf4<<<dim3(2048, BATCH), 256>>>(x, XH, 524288, (size_t)CH * HW, (size_t)CH * HW);

    // K1: projections (2-term), routed epilogue
    gemm_mma<2, 32, 3, 128, 2><<<dim3(7, 32, BATCH), 256, SM_AT2>>>(
        WH, WL, XH, BI, Y, 512, 512, HW, HW,
        (size_t)0, (size_t)CH * HW, (size_t)MPAD * HW, 1, QTH, KH, VH,
        nullptr, nullptr);

    // ---- fork: channel path on s2 ----
    cudaEventRecord(evFork, 0);
    cudaStreamWaitEvent(s2, evFork, 0);

    chan_energy<<<dim3(16, BATCH), 256, 0, s2>>>(
        Y + (size_t)640 * HW, Y + (size_t)704 * HW, CEP);
    reduce_ce<<<128, 256, 0, s2>>>(CEP, CE);
    chan_softmax<<<BATCH * 64, 64, 0, s2>>>(CE);
    chan_out<<<dim3(16, BATCH), 256, 0, s2>>>(CE, Y + (size_t)768 * HW, CO);
    cudaEventRecord(evJoin, s2);

    // ---- main stream: position path ----
    gemm_mma<1, 32, 3, 128, 2><<<dim3(32, 32, BATCH), 256, SM_AT1>>>(
        QTH, nullptr, KH, nullptr, nullptr, 64, 64, HW, 0,
        (size_t)HW * 64, (size_t)64 * HW, (size_t)0, 0,
        nullptr, nullptr, nullptr, PH, PART);

    zinv_k<<<BATCH * HW / 256, 256>>>(PART, ZINV);
    vscale_k<<<dim3(4096, BATCH), 256>>>(VH, ZINV);

    // K4: pos_out = vscaled @ PE
    gemm_mma<1, 32, 3, 128, 2><<<dim3(4, 32, BATCH), 256, SM_AT1>>>(
        VH, nullptr, PH, nullptr, out, HW, HW, HW, HW,
        (size_t)CH * HW, (size_t)HW * HW, (size_t)CH * HW, 0,
        nullptr, nullptr, nullptr, nullptr, nullptr);

    // ---- join ----
    cudaStreamWaitEvent(0, evJoin, 0);

    // K8: d_out += co_w @ c_out + co_b (SIMT)
    gemm_acc<<<dim3(32, 4, BATCH), 256>>>(
        (const float*)d_in[13], CO, (const float*)d_in[14], out,
        CH, HW, CQD, CQD, HW, HW,
        (size_t)0, (size_t)CQD * HW, (size_t)CH * HW);
}

// round 16
// speedup vs baseline: 1.2594x; 1.0693x over previous
#include <cuda_runtime.h>
#include <cuda_fp16.h>
#include <cstdint>
#include <cstddef>

// ---------------------------------------------------------------------------
// Problem constants
// ---------------------------------------------------------------------------
#define BATCH 8
#define CH    512
#define CQD   64
#define HW    4096
#define M2TOT 320          // K1a packed rows: pq,pk,cq,ck,cv
#define M2PAD 384
#define YROWS 192          // fp32 Y rows per batch (cq,ck,cv)

// scratch layout (float offsets)
#define OFF_BI   0u            // BI2 [384] at 0, BIV [512] at 384
#define OFF_W2H  1024u         // [384,512] fp16
#define OFF_W2L  99328u
#define OFF_WVH  197632u       // [512,512] fp16 (v weights, hi only)
#define OFF_XH   328704u       // [8,512,4096] fp16
#define OFF_Y    8717312u      // [8,192,4096] fp32 (cq,ck,cv)
#define OFF_QTH  15008768u     // [8,4096,64] fp16
#define OFF_KH   16057344u     // [8,64,4096] fp16
#define OFF_VH   17105920u     // [8,512,4096] fp16
#define OFF_PH   25494528u     // PE fp16 [8,4096,4096]
#define OFF_PART 92603392u     // [8,32,4096] fp32
#define OFF_ZINV 93651968u
#define OFF_CE   93684736u
#define OFF_CEP  93717504u
#define OFF_CO   94241792u
#define SCRATCH_FLOATS 96338944u

__device__ float g_scratch[SCRATCH_FLOATS];

// ---------------------------------------------------------------------------
// PTX helpers
// ---------------------------------------------------------------------------
__device__ __forceinline__ uint32_t smem_to_u32(const void* p) {
    uint32_t a;
    asm("{ .reg .u64 t; cvta.to.shared.u64 t, %1; cvt.u32.u64 %0, t; }" : "=r"(a) : "l"(p));
    return a;
}

__device__ __forceinline__ void ldsm4(uint32_t* r, uint32_t addr) {
    asm volatile("ldmatrix.sync.aligned.m8n8.x4.shared.b16 {%0,%1,%2,%3}, [%4];"
                 : "=r"(r[0]), "=r"(r[1]), "=r"(r[2]), "=r"(r[3]) : "r"(addr));
}
__device__ __forceinline__ void ldsm4t(uint32_t* r, uint32_t addr) {
    asm volatile("ldmatrix.sync.aligned.m8n8.x4.trans.shared.b16 {%0,%1,%2,%3}, [%4];"
                 : "=r"(r[0]), "=r"(r[1]), "=r"(r[2]), "=r"(r[3]) : "r"(addr));
}
__device__ __forceinline__ void mma16816(float* c, const uint32_t* a,
                                         uint32_t b0, uint32_t b1) {
    asm volatile("mma.sync.aligned.m16n8k16.row.col.f32.f16.f16.f32 "
                 "{%0,%1,%2,%3}, {%4,%5,%6,%7}, {%8,%9}, {%0,%1,%2,%3};"
                 : "+f"(c[0]), "+f"(c[1]), "+f"(c[2]), "+f"(c[3])
                 : "r"(a[0]), "r"(a[1]), "r"(a[2]), "r"(a[3]), "r"(b0), "r"(b1));
}
__device__ __forceinline__ void cp16(uint32_t dst, const void* src) {
    asm volatile("cp.async.cg.shared.global [%0], [%1], 16;" :: "r"(dst), "l"(src));
}
#define CP_COMMIT() asm volatile("cp.async.commit_group;" ::: "memory")

// ---------------------------------------------------------------------------
// fp16-split GEMM via mma.sync (HMMA) — proven R8/R12 config.
// Epilogue modes (checked in order):
//   KHo != nullptr : K1a routing — row<64 -> QTo transposed fp16;
//       row<128 -> KHo fp16; row<320 -> fp32 C at (row-128); else skip.
//   VHo != nullptr : K1b — all rows -> VHo fp16 (+bias)
//   PEo != nullptr : K2 exp epilogue (PE fp16 + row-sum partials)
//   else           : fp32 C (+bias)
// ---------------------------------------------------------------------------
template<int AT, int BK, int NST, int BN, int OCC>
__global__ void __launch_bounds__(256, OCC) gemm_mma(
    const __half* __restrict__ Ah, const __half* __restrict__ Al,
    const __half* __restrict__ Bh,
    const float* __restrict__ bias, float* __restrict__ C,
    int K, int lda, int ldb, int ldc,
    size_t sA, size_t sB, size_t sC, int has_bias,
    __half* __restrict__ QTo, __half* __restrict__ KHo, __half* __restrict__ VHo,
    __half* __restrict__ PEo, float* __restrict__ Part)
{
    constexpr int APITCH = BK + 8;
    constexpr int BPITCH = BN + 8;
    constexpr int A_STG  = 128 * APITCH * 2;
    constexpr int B_STG  = BK * BPITCH * 2;
    constexpr int STG_BYTES = AT * A_STG + B_STG;
    constexpr int ATPR  = BK / 8;
    constexpr int AROWS = 256 / ATPR;
    constexpr int NPASS = 128 / AROWS;
    constexpr int BTPR  = BN / 8;
    constexpr int BROWS = 256 / BTPR;
    constexpr int BPASS = BK / BROWS;
    constexpr int KS    = BK / 16;
    constexpr int NJ    = BN / 32;
    constexpr int WN    = BN / 2;

    extern __shared__ char smem[];
    __shared__ float sred[2][128];
    const uint32_t sb = smem_to_u32(smem);
    const int tid  = threadIdx.x;
    const int w    = tid >> 5, lane = tid & 31;
    const int wm   = w & 3,    wn   = w >> 2;
    const int b    = blockIdx.z;
    const int m0   = blockIdx.x * 128, n0 = blockIdx.y * BN;

    const __half* Ag[AT];
    Ag[0] = Ah + (size_t)b * sA + (size_t)m0 * lda;
    if (AT == 2) Ag[1] = Al + (size_t)b * sA + (size_t)m0 * lda;
    const __half* Bg0 = Bh + (size_t)b * sB + n0;

    const int nk = K / BK;

    const int a_row = tid / ATPR, a_ch = (tid % ATPR) << 3;
    const int b_row = tid / BTPR, b_ch = (tid % BTPR) << 3;

    auto issue = [&](int stage, int kt) {
        const uint32_t base = sb + stage * STG_BYTES;
        const int k0 = kt * BK;
#pragma unroll
        for (int h = 0; h < AT; h++) {
            const __half* asrc = Ag[h] + k0;
            const uint32_t adst = base + h * A_STG;
#pragma unroll
            for (int r = 0; r < NPASS; r++) {
                int row = a_row + r * AROWS;
                cp16(adst + (uint32_t)(row * APITCH + a_ch) * 2,
                     asrc + (size_t)row * lda + a_ch);
            }
        }
        {
            const uint32_t bdst = base + AT * A_STG;
#pragma unroll
            for (int r = 0; r < BPASS; r++) {
                int row = b_row + r * BROWS;
                cp16(bdst + (uint32_t)(row * BPITCH + b_ch) * 2,
                     Bg0 + (size_t)(k0 + row) * ldb + b_ch);
            }
        }
    };

    float c[2][2 * NJ][4];
#pragma unroll
    for (int mi = 0; mi < 2; mi++)
#pragma unroll
        for (int j = 0; j < 2 * NJ; j++)
#pragma unroll
            for (int q = 0; q < 4; q++) c[mi][j][q] = 0.0f;

#pragma unroll
    for (int s = 0; s < NST - 1; s++) {
        if (s < nk) issue(s, s);
        CP_COMMIT();
    }

    const uint32_t a_lane_off = (uint32_t)((lane & 15) * APITCH + ((lane >> 4) << 3)) * 2;
    const uint32_t b_lane_off = (uint32_t)((lane & 15) * BPITCH + ((lane >> 4) << 3)) * 2;

    for (int kt = 0; kt < nk; kt++) {
        const int kf = kt + NST - 1;
        if (kf < nk) issue(kf % NST, kf);
        CP_COMMIT();
        asm volatile("cp.async.wait_group %0;" :: "n"(NST - 1) : "memory");
        __syncthreads();

        const int stage = kt % NST;
        const uint32_t ab = sb + stage * STG_BYTES;
        const uint32_t bb = ab + AT * A_STG;

#pragma unroll
        for (int ks = 0; ks < KS; ks++) {
            uint32_t afr[AT][2][4];
            uint32_t bfr[NJ][4];
#pragma unroll
            for (int h = 0; h < AT; h++)
#pragma unroll
                for (int mi = 0; mi < 2; mi++)
                    ldsm4(afr[h][mi],
                          ab + h * A_STG + a_lane_off +
                          (uint32_t)((wm * 32 + mi * 16) * APITCH + ks * 16) * 2);
#pragma unroll
            for (int nj = 0; nj < NJ; nj++)
                ldsm4t(bfr[nj],
                       bb + b_lane_off +
                       (uint32_t)(ks * 16 * BPITCH + wn * WN + nj * 16) * 2);
#pragma unroll
            for (int mi = 0; mi < 2; mi++)
#pragma unroll
                for (int j = 0; j < 2 * NJ; j++) {
                    const int nj = j >> 1, hf = (j & 1) << 1;
                    mma16816(c[mi][j], afr[0][mi], bfr[nj][hf], bfr[nj][hf + 1]);
                    if (AT == 2)
                        mma16816(c[mi][j], afr[1][mi], bfr[nj][hf], bfr[nj][hf + 1]);
                }
        }
        __syncthreads();
    }

    // ---- epilogue ----
    const int colbase = n0 + wn * WN + (lane & 3) * 2;
    if (KHo != nullptr) {
        // K1a routing
#pragma unroll
        for (int mi = 0; mi < 2; mi++)
#pragma unroll
            for (int rr = 0; rr < 2; rr++) {
                const int row = m0 + wm * 32 + mi * 16 + (lane >> 2) + rr * 8;
                if (row >= M2TOT) continue;
                const float bv = bias[row];
                if (row < 64) {
                    __half* qb = QTo + (size_t)b * HW * 64 + row;
#pragma unroll
                    for (int j = 0; j < 2 * NJ; j++) {
                        const int col = colbase + j * 8;
                        qb[(size_t)col * 64]       =
                            __float2half_rn(c[mi][j][rr * 2] + bv);
                        qb[(size_t)(col + 1) * 64] =
                            __float2half_rn(c[mi][j][rr * 2 + 1] + bv);
                    }
                } else if (row < 128) {
                    __half* ph = KHo + ((size_t)b * 64 + (row - 64)) * HW + colbase;
#pragma unroll
                    for (int j = 0; j < 2 * NJ; j++)
                        *reinterpret_cast<__half2*>(ph + j * 8) = __halves2half2(
                            __float2half_rn(c[mi][j][rr * 2] + bv),
                            __float2half_rn(c[mi][j][rr * 2 + 1] + bv));
                } else {
                    float* p = C + (size_t)b * sC + (size_t)(row - 128) * ldc + colbase;
#pragma unroll
                    for (int j = 0; j < 2 * NJ; j++)
                        *reinterpret_cast<float2*>(p + j * 8) =
                            make_float2(c[mi][j][rr * 2] + bv, c[mi][j][rr * 2 + 1] + bv);
                }
            }
    } else if (VHo != nullptr) {
        // K1b: all rows -> VH fp16 (+bias)
#pragma unroll
        for (int mi = 0; mi < 2; mi++)
#pragma unroll
            for (int rr = 0; rr < 2; rr++) {
                const int row = m0 + wm * 32 + mi * 16 + (lane >> 2) + rr * 8;
                const float bv = bias[row];
                __half* ph = VHo + ((size_t)b * 512 + row) * HW + colbase;
#pragma unroll
                for (int j = 0; j < 2 * NJ; j++)
                    *reinterpret_cast<__half2*>(ph + j * 8) = __halves2half2(
                        __float2half_rn(c[mi][j][rr * 2] + bv),
                        __float2half_rn(c[mi][j][rr * 2 + 1] + bv));
            }
    } else if (PEo != nullptr) {
#pragma unroll
        for (int mi = 0; mi < 2; mi++)
#pragma unroll
            for (int rr = 0; rr < 2; rr++) {
                const int rloc = wm * 32 + mi * 16 + (lane >> 2) + rr * 8;
                __half* pp = PEo + ((size_t)b * HW + m0 + rloc) * HW + colbase;
                float rsum = 0.0f;
#pragma unroll
                for (int j = 0; j < 2 * NJ; j++) {
                    float e0 = __expf(c[mi][j][rr * 2]     - 8.0f);
                    float e1 = __expf(c[mi][j][rr * 2 + 1] - 8.0f);
                    __half h0 = __float2half_rn(e0), h1 = __float2half_rn(e1);
                    *reinterpret_cast<__half2*>(pp + j * 8) = __halves2half2(h0, h1);
                    rsum += __half2float(h0) + __half2float(h1);
                }
                rsum += __shfl_xor_sync(0xffffffffu, rsum, 1);
                rsum += __shfl_xor_sync(0xffffffffu, rsum, 2);
                if ((lane & 3) == 0) sred[wn][rloc] = rsum;
            }
        __syncthreads();
        if (tid < 128) {
            float z = sred[0][tid] + sred[1][tid];
            Part[((size_t)b * gridDim.y + blockIdx.y) * HW + m0 + tid] = z;
        }
    } else {
#pragma unroll
        for (int mi = 0; mi < 2; mi++) {
            const int r0 = m0 + wm * 32 + mi * 16 + (lane >> 2);
            const float bv0 = has_bias ? bias[r0]     : 0.0f;
            const float bv1 = has_bias ? bias[r0 + 8] : 0.0f;
            float* p0 = C + (size_t)b * sC + (size_t)r0 * ldc + colbase;
            float* p1 = p0 + (size_t)8 * ldc;
#pragma unroll
            for (int j = 0; j < 2 * NJ; j++) {
                *reinterpret_cast<float2*>(p0 + j * 8) =
                    make_float2(c[mi][j][0] + bv0, c[mi][j][1] + bv0);
                *reinterpret_cast<float2*>(p1 + j * 8) =
                    make_float2(c[mi][j][2] + bv1, c[mi][j][3] + bv1);
            }
        }
    }
}

#define SM_AT2 (3 * (2 * 128 * 40 * 2 + 32 * 136 * 2))   // 87552
#define SM_AT1 (3 * (1 * 128 * 40 * 2 + 32 * 136 * 2))   // 56832

// ---------------------------------------------------------------------------
// Z reduction + v column scaling
// ---------------------------------------------------------------------------
__global__ void zinv_k(const float* __restrict__ Part, float* __restrict__ zinv)
{
    int i = blockIdx.x * 256 + threadIdx.x;
    int b = i >> 12, r = i & 4095;
    float s = 0.0f;
#pragma unroll
    for (int jt = 0; jt < 32; jt++) s += Part[((size_t)b * 32 + jt) * HW + r];
    zinv[i] = 1.0f / s;
}

__global__ void vscale_k(__half* __restrict__ VH, const float* __restrict__ zinv)
{
    const int b = blockIdx.y;
    int idx = blockIdx.x * 256 + threadIdx.x;
    int c  = idx >> 11;
    int i2 = idx & 2047;
    __half2* p = reinterpret_cast<__half2*>(VH + ((size_t)b * 512 + c) * HW) + i2;
    float2 f = __half22float2(*p);
    float z0 = zinv[(size_t)b * HW + 2 * i2];
    float z1 = zinv[(size_t)b * HW + 2 * i2 + 1];
    *p = __floats2half2_rn(f.x * z0, f.y * z1);
}

// ---------------------------------------------------------------------------
// fp16 conversions / packing (direct from inputs)
// ---------------------------------------------------------------------------
__global__ void tohalf4(const float* __restrict__ in, __half* __restrict__ hi,
                        int count4, size_t in_bs, size_t out_bs)
{
    size_t b = blockIdx.y;
    int i = blockIdx.x * 256 + threadIdx.x;
    if (i >= count4) return;
    float4 v = reinterpret_cast<const float4*>(in + b * in_bs)[i];
    __half2* ph = reinterpret_cast<__half2*>(hi + b * out_bs);
    ph[2 * i]     = __floats2half2_rn(v.x, v.y);
    ph[2 * i + 1] = __floats2half2_rn(v.z, v.w);
}

// pack+split 5 small weight matrices: pq 0-63, pk 64-127, cq 128-191,
// ck 192-255, cv 256-319, zero to 383
__global__ void splitW5(const float* __restrict__ pq, const float* __restrict__ pk,
                        const float* __restrict__ cq, const float* __restrict__ ck,
                        const float* __restrict__ cv,
                        __half* __restrict__ hi, __half* __restrict__ lo)
{
    int i = blockIdx.x * 256 + threadIdx.x;     // 0 .. M2PAD*CH-1
    int row = i >> 9;
    int col = i & 511;
    float v = 0.0f;
    if (row < 64)        v = pq[(size_t)row * 512 + col];
    else if (row < 128)  v = pk[(size_t)(row - 64) * 512 + col];
    else if (row < 192)  v = cq[(size_t)(row - 128) * 512 + col];
    else if (row < 256)  v = ck[(size_t)(row - 192) * 512 + col];
    else if (row < 320)  v = cv[(size_t)(row - 256) * 512 + col];
    __half h = __float2half_rn(v);
    hi[i] = h;
    lo[i] = __float2half_rn(v - __half2float(h));
}

// v weights -> fp16 hi only
__global__ void tohalfW(const float* __restrict__ in, __half* __restrict__ hi, int n)
{
    int i = blockIdx.x * 256 + threadIdx.x;
    if (i < n) hi[i] = __float2half_rn(in[i]);
}

// pack biases: BI2[0..383] (pq,pk,cq,ck,cv), BIV[0..511] (pv)
__global__ void bias_pack(const float* __restrict__ pqb, const float* __restrict__ pkb,
                          const float* __restrict__ cqb, const float* __restrict__ ckb,
                          const float* __restrict__ cvb, const float* __restrict__ pvb,
                          float* __restrict__ BI2, float* __restrict__ BIV)
{
    int i = blockIdx.x * 128 + threadIdx.x;     // 0 .. 895
    if (i < 384) {
        float v = 0.0f;
        if (i < 64)        v = pqb[i];
        else if (i < 128)  v = pkb[i - 64];
        else if (i < 192)  v = cqb[i - 128];
        else if (i < 256)  v = ckb[i - 192];
        else if (i < 320)  v = cvb[i - 256];
        BI2[i] = v;
    } else if (i < 896) {
        BIV[i - 384] = pvb[i - 384];
    }
}

// ---------------------------------------------------------------------------
// SIMT f32x2 GEMM (small K8 accumulate)
// ---------------------------------------------------------------------------
__device__ __forceinline__ unsigned long long pk2(float lo, float hi) {
    unsigned long long r;
    asm("mov.b64 %0, {%1, %2};" : "=l"(r) : "f"(lo), "f"(hi));
    return r;
}
__device__ __forceinline__ unsigned long long fma2(unsigned long long a,
                                                   unsigned long long b,
                                                   unsigned long long c) {
    unsigned long long d;
    asm("fma.rn.f32x2 %0, %1, %2, %3;" : "=l"(d) : "l"(a), "l"(b), "l"(c));
    return d;
}
__device__ __forceinline__ float2 u2f(unsigned long long u) {
    float2 f;
    asm("mov.b64 {%0, %1}, %2;" : "=f"(f.x), "=f"(f.y) : "l"(u));
    return f;
}

__global__ __launch_bounds__(256, 2)
void gemm_acc(const float* __restrict__ A, const float* __restrict__ Bm,
              const float* __restrict__ bias, float* __restrict__ Cm,
              int M, int N, int K, int lda, int ldb, int ldc,
              size_t sA, size_t sB, size_t sC)
{
    __shared__ float As[16][128 + 4];
    __shared__ float Bs[16][128];

    const int b  = blockIdx.z;
    const float* Ab = A + (size_t)b * sA;
    const float* Bb = Bm + (size_t)b * sB;
    float*       Cb = Cm + (size_t)b * sC;

    const int m0 = blockIdx.y * 128;
    const int n0 = blockIdx.x * 128;
    const int t  = threadIdx.x;
    const int tm0 = (t >> 4) << 3;
    const int tn0 = (t & 15) << 3;

    unsigned long long acc[8][4];
#pragma unroll
    for (int i = 0; i < 8; i++)
#pragma unroll
        for (int j = 0; j < 4; j++) acc[i][j] = 0ull;

    for (int k0 = 0; k0 < K; k0 += 16) {
#pragma unroll
        for (int r = 0; r < 2; r++) {
            int idx = t + r * 256;
            int row = idx >> 2;
            int c4  = (idx & 3) << 2;
            float4 v = make_float4(0.f, 0.f, 0.f, 0.f);
            if (m0 + row < M)
                v = *reinterpret_cast<const float4*>(Ab + (size_t)(m0 + row) * lda + k0 + c4);
            As[c4 + 0][row] = v.x; As[c4 + 1][row] = v.y;
            As[c4 + 2][row] = v.z; As[c4 + 3][row] = v.w;
        }
#pragma unroll
        for (int r = 0; r < 2; r++) {
            int idx = t + r * 256;
            int kr  = idx >> 5;
            int n4  = (idx & 31) << 2;
            float4 v = *reinterpret_cast<const float4*>(Bb + (size_t)(k0 + kr) * ldb + n0 + n4);
            *reinterpret_cast<float4*>(&Bs[kr][n4]) = v;
        }
        __syncthreads();
#pragma unroll
        for (int kk = 0; kk < 16; kk++) {
            float4 a0 = *reinterpret_cast<const float4*>(&As[kk][tm0]);
            float4 a1 = *reinterpret_cast<const float4*>(&As[kk][tm0 + 4]);
            ulonglong2 bl0 = *reinterpret_cast<const ulonglong2*>(&Bs[kk][tn0]);
            ulonglong2 bl1 = *reinterpret_cast<const ulonglong2*>(&Bs[kk][tn0 + 4]);
            unsigned long long bv[4] = {bl0.x, bl0.y, bl1.x, bl1.y};
            float av[8] = {a0.x, a0.y, a0.z, a0.w, a1.x, a1.y, a1.z, a1.w};
#pragma unroll
            for (int i = 0; i < 8; i++) {
                unsigned long long a2 = pk2(av[i], av[i]);
#pragma unroll
                for (int j = 0; j < 4; j++) acc[i][j] = fma2(a2, bv[j], acc[i][j]);
            }
        }
        __syncthreads();
    }
#pragma unroll
    for (int i = 0; i < 8; i++) {
        int m = m0 + tm0 + i;
        if (m >= M) continue;
        float bsv = bias[m];
        float* crow = Cb + (size_t)m * ldc + n0 + tn0;
#pragma unroll
        for (int j = 0; j < 4; j++) {
            float2 f = u2f(acc[i][j]);
            float2 o = *reinterpret_cast<const float2*>(crow + j * 2);
            f.x += bsv + o.x; f.y += bsv + o.y;
            *reinterpret_cast<float2*>(crow + j * 2) = f;
        }
    }
}

// ---------------------------------------------------------------------------
// Channel attention kernels (fp32, small; Y has 192 rows/batch: cq 0, ck 64, cv 128)
// ---------------------------------------------------------------------------
__global__ void chan_energy(const float* __restrict__ cq, const float* __restrict__ ck,
                            float* __restrict__ part)
{
    __shared__ float sq[64][65];
    __shared__ float sk[64][65];
    const int b = blockIdx.y;
    const int split = blockIdx.x;
    const float* cqb = cq + (size_t)b * YROWS * HW;
    const float* ckb = ck + (size_t)b * YROWS * HW;
    const int t = threadIdx.x;
    const int p0 = (t >> 4) * 4;
    const int q0 = (t & 15) * 4;

    float acc[4][4];
#pragma unroll
    for (int i = 0; i < 4; i++)
#pragma unroll
        for (int j = 0; j < 4; j++) acc[i][j] = 0.f;

    for (int c = 0; c < 4; c++) {
        const int nb = (split * 4 + c) * 64;
        __syncthreads();
#pragma unroll
        for (int i = 0; i < 16; i++) {
            int idx = t + i * 256;
            int row = idx >> 6, col = idx & 63;
            sq[row][col] = cqb[(size_t)row * HW + nb + col];
            sk[row][col] = ckb[(size_t)row * HW + nb + col];
        }
        __syncthreads();
        for (int nn = 0; nn < 64; nn++) {
            float aq[4], bk[4];
#pragma unroll
            for (int i = 0; i < 4; i++) aq[i] = sq[p0 + i][nn];
#pragma unroll
            for (int j = 0; j < 4; j++) bk[j] = sk[q0 + j][nn];
#pragma unroll
            for (int i = 0; i < 4; i++)
#pragma unroll
                for (int j = 0; j < 4; j++) acc[i][j] += aq[i] * bk[j];
        }
    }
    float* out = part + (size_t)split * (BATCH * 4096) + (size_t)b * 4096;
#pragma unroll
    for (int i = 0; i < 4; i++)
#pragma unroll
        for (int j = 0; j < 4; j++)
            out[(p0 + i) * 64 + (q0 + j)] = acc[i][j];
}

__global__ void reduce_ce(const float* __restrict__ part, float* __restrict__ cE)
{
    int i = blockIdx.x * 256 + threadIdx.x;
    float s = 0.f;
#pragma unroll
    for (int k = 0; k < 16; k++) s += part[(size_t)k * (BATCH * 4096) + i];
    cE[i] = s;
}

__global__ void chan_softmax(float* __restrict__ cE)
{
    __shared__ float red[64];
    const int row = blockIdx.x;
    float* rp = cE + (size_t)row * 64;
    const int t = threadIdx.x;
    float v = rp[t];
    red[t] = v; __syncthreads();
    for (int s = 32; s > 0; s >>= 1) {
        if (t < s) red[t] = fmaxf(red[t], red[t + s]);
        __syncthreads();
    }
    float m = red[0]; __syncthreads();
    float e = __expf(v - m);
    red[t] = e; __syncthreads();
    for (int s = 32; s > 0; s >>= 1) {
        if (t < s) red[t] += red[t + s];
        __syncthreads();
    }
    rp[t] = e / red[0];
}

__global__ void chan_out(const float* __restrict__ cattn, const float* __restrict__ cv,
                         float* __restrict__ cout)
{
    __shared__ float sa[4096];
    const int b = blockIdx.y;
    const int n = blockIdx.x * 256 + threadIdx.x;
    const float* at = cattn + (size_t)b * 4096;
    for (int i = threadIdx.x; i < 4096; i += 256) sa[i] = at[i];
    __syncthreads();

    const float* cvb = cv + (size_t)b * YROWS * HW;
    float acc[64];
#pragma unroll
    for (int p = 0; p < 64; p++) acc[p] = 0.f;
    for (int q = 0; q < 64; q++) {
        float vv = cvb[(size_t)q * HW + n];
#pragma unroll
        for (int p = 0; p < 64; p++) acc[p] += sa[p * 64 + q] * vv;
    }
    float* ob = cout + (size_t)b * CQD * HW;
#pragma unroll
    for (int p = 0; p < 64; p++) ob[(size_t)p * HW + n] = acc[p];
}

// ---------------------------------------------------------------------------
// Launch: two-stream; s2 carries K1b (v projection) + channel path
// ---------------------------------------------------------------------------
extern "C" void kernel_launch(void* const* d_in, const int* in_sizes, int n_in,
                              void* d_out, int out_size)
{
    (void)in_sizes; (void)n_in; (void)out_size;

    static cudaStream_t s2 = nullptr;
    static cudaEvent_t evFork = nullptr, evV = nullptr, evJoin = nullptr;
    if (s2 == nullptr) {
        cudaStreamCreateWithFlags(&s2, cudaStreamNonBlocking);
        cudaEventCreateWithFlags(&evFork, cudaEventDisableTiming);
        cudaEventCreateWithFlags(&evV, cudaEventDisableTiming);
        cudaEventCreateWithFlags(&evJoin, cudaEventDisableTiming);
    }

    const float* x = (const float*)d_in[0];

    float* S = nullptr;
    cudaGetSymbolAddress((void**)&S, g_scratch);

    float* BI2  = S + OFF_BI;
    float* BIV  = S + OFF_BI + 384;
    float* Y    = S + OFF_Y;
    float* PART = S + OFF_PART;
    float* ZINV = S + OFF_ZINV;
    float* CE   = S + OFF_CE;
    float* CEP  = S + OFF_CEP;
    float* CO   = S + OFF_CO;
    float* out  = (float*)d_out;

    __half* W2H = (__half*)(S + OFF_W2H);
    __half* W2L = (__half*)(S + OFF_W2L);
    __half* WVH = (__half*)(S + OFF_WVH);
    __half* XH  = (__half*)(S + OFF_XH);
    __half* QTH = (__half*)(S + OFF_QTH);
    __half* KH  = (__half*)(S + OFF_KH);
    __half* VH  = (__half*)(S + OFF_VH);
    __half* PH  = (__half*)(S + OFF_PH);

    cudaFuncSetAttribute((const void*)gemm_mma<2, 32, 3, 128, 2>,
                         cudaFuncAttributeMaxDynamicSharedMemorySize, SM_AT2);
    cudaFuncSetAttribute((const void*)gemm_mma<1, 32, 3, 128, 2>,
                         cudaFuncAttributeMaxDynamicSharedMemorySize, SM_AT1);

    // packing / conversions (direct from inputs)
    splitW5<<<(M2PAD * CH + 255) / 256, 256>>>(
        (const float*)d_in[1], (const float*)d_in[3], (const float*)d_in[7],
        (const float*)d_in[9], (const float*)d_in[11], W2H, W2L);
    tohalfW<<<(CH * CH + 255) / 256, 256>>>((const float*)d_in[5], WVH, CH * CH);
    bias_pack<<<7, 128>>>(
        (const float*)d_in[2], (const float*)d_in[4], (const float*)d_in[8],
        (const float*)d_in[10], (const float*)d_in[12], (const float*)d_in[6],
        BI2, BIV);
    tohalf4<<<dim3(2048, BATCH), 256>>>(x, XH, 524288, (size_t)CH * HW, (size_t)CH * HW);

    // K1a: q,k,channel projections (2-term), routed epilogue
    gemm_mma<2, 32, 3, 128, 2><<<dim3(3, 32, BATCH), 256, SM_AT2>>>(
        W2H, W2L, XH, BI2, Y, 512, 512, HW, HW,
        (size_t)0, (size_t)CH * HW, (size_t)YROWS * HW, 1, QTH, KH, nullptr,
        nullptr, nullptr);

    // ---- fork: K1b (v projection) + channel path on s2 ----
    cudaEventRecord(evFork, 0);
    cudaStreamWaitEvent(s2, evFork, 0);

    // K1b: v = fp16(Wv @ x + bias)  (1-term)
    gemm_mma<1, 32, 3, 128, 2><<<dim3(4, 32, BATCH), 256, SM_AT1, s2>>>(
        WVH, nullptr, XH, BIV, nullptr, 512, 512, HW, 0,
        (size_t)0, (size_t)CH * HW, (size_t)0, 1, nullptr, nullptr, VH,
        nullptr, nullptr);
    cudaEventRecord(evV, s2);

    chan_energy<<<dim3(16, BATCH), 256, 0, s2>>>(Y, Y + (size_t)64 * HW, CEP);
    reduce_ce<<<128, 256, 0, s2>>>(CEP, CE);
    chan_softmax<<<BATCH * 64, 64, 0, s2>>>(CE);
    chan_out<<<dim3(16, BATCH), 256, 0, s2>>>(CE, Y + (size_t)128 * HW, CO);
    cudaEventRecord(evJoin, s2);

    // ---- main stream: position path ----
    gemm_mma<1, 32, 3, 128, 2><<<dim3(32, 32, BATCH), 256, SM_AT1>>>(
        QTH, nullptr, KH, nullptr, nullptr, 64, 64, HW, 0,
        (size_t)HW * 64, (size_t)64 * HW, (size_t)0, 0,
        nullptr, nullptr, nullptr, PH, PART);

    zinv_k<<<BATCH * HW / 256, 256>>>(PART, ZINV);

    // vscale needs VH from K1b
    cudaStreamWaitEvent(0, evV, 0);
    vscale_k<<<dim3(4096, BATCH), 256>>>(VH, ZINV);

    // K4: pos_out = vscaled @ PE
    gemm_mma<1, 32, 3, 128, 2><<<dim3(4, 32, BATCH), 256, SM_AT1>>>(
        VH, nullptr, PH, nullptr, out, HW, HW, HW, HW,
        (size_t)CH * HW, (size_t)HW * HW, (size_t)CH * HW, 0,
        nullptr, nullptr, nullptr, nullptr, nullptr);

    // ---- join ----
    cudaStreamWaitEvent(0, evJoin, 0);

    // K8: d_out += co_w @ c_out + co_b (SIMT)
    gemm_acc<<<dim3(32, 4, BATCH), 256>>>(
        (const float*)d_in[13], CO, (const float*)d_in[14], out,
        CH, HW, CQD, CQD, HW, HW,
        (size_t)0, (size_t)CQD * HW, (size_t)CH * HW);
}